// round 2
// baseline (speedup 1.0000x reference)
#include <cuda_runtime.h>
#include <math.h>

#define B_ 4
#define T_ 512
#define TAU_ 512
#define L_ 1024
#define DM_ 1024
#define H_ 16
#define D_ 64

// ---------------- scratch (device globals; no allocations allowed) ----------
__device__ float g_xln[B_ * L_ * DM_];        // 16 MB  LN(concat(mem, inp))
__device__ float g_qkv[B_ * L_ * 3 * DM_];    // 48 MB  [B,L,3072]
__device__ float g_phi[L_ * DM_];             //  4 MB
__device__ float g_R[L_ * DM_];               //  4 MB  [L, H*D]
__device__ float g_attn[B_ * T_ * DM_];       //  8 MB  [B,T,H*D]

// ---------------- LayerNorm over concat(memory, inputs) ---------------------
__global__ __launch_bounds__(256) void ln_kernel(const float* __restrict__ inputs,
                          const float* __restrict__ memory,
                          const float* __restrict__ gamma,
                          const float* __restrict__ beta) {
    int row = blockIdx.x;                 // 0..B*L-1
    int b = row >> 10, l = row & 1023;
    const float* src = (l < TAU_) ? memory + ((size_t)b * TAU_ + l) * DM_
                                  : inputs + ((size_t)b * T_ + (l - TAU_)) * DM_;
    int tid = threadIdx.x;                // 256 threads, 4 floats each
    float4 x = ((const float4*)src)[tid];
    float s  = x.x + x.y + x.z + x.w;
    float ss = x.x * x.x + x.y * x.y + x.z * x.z + x.w * x.w;
#pragma unroll
    for (int off = 16; off; off >>= 1) {
        s  += __shfl_xor_sync(0xffffffffu, s, off);
        ss += __shfl_xor_sync(0xffffffffu, ss, off);
    }
    __shared__ float red[16];
    int wid = tid >> 5, lane = tid & 31;
    if (lane == 0) { red[wid] = s; red[8 + wid] = ss; }
    __syncthreads();
    float ts = 0.f, tss = 0.f;
#pragma unroll
    for (int i = 0; i < 8; i++) { ts += red[i]; tss += red[8 + i]; }
    float mu   = ts * (1.0f / DM_);
    float var  = tss * (1.0f / DM_) - mu * mu;
    float rstd = rsqrtf(var + 1e-5f);
    float4 g  = ((const float4*)gamma)[tid];
    float4 bb = ((const float4*)beta)[tid];
    float4 o;
    o.x = (x.x - mu) * rstd * g.x + bb.x;
    o.y = (x.y - mu) * rstd * g.y + bb.y;
    o.z = (x.z - mu) * rstd * g.z + bb.z;
    o.w = (x.w - mu) * rstd * g.w + bb.w;
    ((float4*)(g_xln + (size_t)row * DM_))[tid] = o;
}

// ---------------- positional features phi[l, :] ------------------------------
__global__ __launch_bounds__(256) void phi_kernel() {
    int l = blockIdx.x;
    float pos = (float)(L_ - 1 - l);
    for (int f = threadIdx.x; f < 512; f += blockDim.x) {
        float ex  = (float)(2 * f) / 1024.0f;
        float inv = powf(10000.0f, -ex);
        float a = pos * inv;
        float sn, cs;
        sincosf(a, &sn, &cs);
        g_phi[(size_t)l * DM_ + f]       = sn;
        g_phi[(size_t)l * DM_ + 512 + f] = cs;
    }
}

// ---------------- C[M,N] = A[M,K] * B[N,K]^T  (fp32, 128x128x8 tiles) --------
__global__ __launch_bounds__(256) void gemm_nt(const float* __restrict__ A, const float* __restrict__ Bm,
                        float* __restrict__ C, int M, int N, int K) {
    __shared__ float sA[8][128];
    __shared__ float sB[8][128];
    int bm = blockIdx.y * 128, bn = blockIdx.x * 128;
    int tid = threadIdx.x;
    int tx = tid & 15, ty = tid >> 4;
    int lr = tid >> 1;
    int lc = (tid & 1) * 4;
    float acc[8][8];
#pragma unroll
    for (int i = 0; i < 8; i++)
#pragma unroll
        for (int j = 0; j < 8; j++) acc[i][j] = 0.f;
    const float* Aptr = A  + (size_t)(bm + lr) * K + lc;
    const float* Bptr = Bm + (size_t)(bn + lr) * K + lc;
    for (int k0 = 0; k0 < K; k0 += 8) {
        float4 a4 = *(const float4*)(Aptr + k0);
        float4 b4 = *(const float4*)(Bptr + k0);
        __syncthreads();
        sA[lc + 0][lr] = a4.x; sA[lc + 1][lr] = a4.y;
        sA[lc + 2][lr] = a4.z; sA[lc + 3][lr] = a4.w;
        sB[lc + 0][lr] = b4.x; sB[lc + 1][lr] = b4.y;
        sB[lc + 2][lr] = b4.z; sB[lc + 3][lr] = b4.w;
        __syncthreads();
#pragma unroll
        for (int k = 0; k < 8; k++) {
            float4 a0 = *(const float4*)&sA[k][ty * 8];
            float4 a1 = *(const float4*)&sA[k][ty * 8 + 4];
            float4 b0 = *(const float4*)&sB[k][tx * 8];
            float4 b1 = *(const float4*)&sB[k][tx * 8 + 4];
            float ar[8] = {a0.x, a0.y, a0.z, a0.w, a1.x, a1.y, a1.z, a1.w};
            float br[8] = {b0.x, b0.y, b0.z, b0.w, b1.x, b1.y, b1.z, b1.w};
#pragma unroll
            for (int i = 0; i < 8; i++)
#pragma unroll
                for (int j = 0; j < 8; j++) acc[i][j] += ar[i] * br[j];
        }
    }
#pragma unroll
    for (int i = 0; i < 8; i++) {
        float* crow = C + (size_t)(bm + ty * 8 + i) * N + bn + tx * 8;
        *(float4*)(crow)     = make_float4(acc[i][0], acc[i][1], acc[i][2], acc[i][3]);
        *(float4*)(crow + 4) = make_float4(acc[i][4], acc[i][5], acc[i][6], acc[i][7]);
    }
}

// ---------------- fused flash attention with relative shift -----------------
// grid: (T/64, B*H), 256 threads. Each block: 64 query rows of one (b,h).
// rel_shift(P)[i,j] = P[i, j + T - 1 - i] for all unmasked (j <= TAU + i).
#define ATP 68
#define ATPR 132
#define ATT_SMEM ((64 * ATP * 5 + 64 * ATPR) * 4)

__global__ __launch_bounds__(256) void attn_kernel(const float* __restrict__ uvar,
                            const float* __restrict__ vvar) {
    extern __shared__ float sm[];
    float* squ = sm;                    // [64 d][ATP]  q + u   (d-major)
    float* sqv = squ + 64 * ATP;        // [64 d][ATP]  q + v
    float* sk  = sqv + 64 * ATP;        // [64 d][ATP]  k tile
    float* sr  = sk + 64 * ATP;         // [64 d][ATPR] 128 R rows
    float* sv  = sr + 64 * ATPR;        // [64 j][ATP]  v tile (j-major)
    float* sp  = sv + 64 * ATP;         // [64 i][ATP]  probs

    int i0 = blockIdx.x * 64;
    int b  = blockIdx.y >> 4;
    int h  = blockIdx.y & 15;
    int tid = threadIdx.x;
    int tx = tid & 15, ty = tid >> 4;
    int iI = ty * 4, jJ = tx * 4;

    // load q tiles once (row = TAU + i0 + i of full sequence)
    for (int e = tid; e < 64 * 64; e += 256) {
        int i = e >> 6, d = e & 63;
        float q = g_qkv[((size_t)(b * L_ + TAU_ + i0 + i)) * 3072 + h * 64 + d];
        squ[d * ATP + i] = q + uvar[h * 64 + d];
        sqv[d * ATP + i] = q + vvar[h * 64 + d];
    }

    float m[4], lsum[4], o[4][4];
#pragma unroll
    for (int ii = 0; ii < 4; ii++) {
        m[ii] = -INFINITY; lsum[ii] = 0.f;
#pragma unroll
        for (int c = 0; c < 4; c++) o[ii][c] = 0.f;
    }

    int ntiles = (TAU_ + i0 + 63) / 64 + 1;   // causal: j <= TAU + i
    for (int jt = 0; jt < ntiles; jt++) {
        int j0 = jt * 64;
        __syncthreads();
        // load K and V tiles
        for (int e = tid; e < 4096; e += 256) {
            int j = e >> 6, d = e & 63;
            size_t base = ((size_t)(b * L_ + j0 + j)) * 3072 + h * 64 + d;
            sk[d * ATP + j] = g_qkv[base + 1024];
            sv[j * ATP + d] = g_qkv[base + 2048];
        }
        // load 128-row R band: rows [rbase, rbase+127]
        int rbase = j0 + T_ - 64 - i0;
        for (int e = tid; e < 8192; e += 256) {
            int r = e >> 6, d = e & 63;
            int rr = rbase + r; rr = rr > (L_ - 1) ? (L_ - 1) : rr;
            sr[d * ATPR + r] = g_R[(size_t)rr * DM_ + h * 64 + d];
        }
        __syncthreads();

        float acc[4][4];
#pragma unroll
        for (int ii = 0; ii < 4; ii++)
#pragma unroll
            for (int jj = 0; jj < 4; jj++) acc[ii][jj] = 0.f;
        int rb = jJ - iI + 60;   // sr offset so rv[3 + jj - ii] is the shifted R row
#pragma unroll 4
        for (int dd = 0; dd < 64; dd++) {
            float4 a  = *(const float4*)(squ + dd * ATP + iI);
            float4 av = *(const float4*)(sqv + dd * ATP + iI);
            float4 bk = *(const float4*)(sk  + dd * ATP + jJ);
            float rv[7];
#pragma unroll
            for (int x = 0; x < 7; x++) rv[x] = sr[dd * ATPR + rb + x];
            float aa[4] = {a.x, a.y, a.z, a.w};
            float vvv[4] = {av.x, av.y, av.z, av.w};
            float bb[4] = {bk.x, bk.y, bk.z, bk.w};
#pragma unroll
            for (int ii = 0; ii < 4; ii++)
#pragma unroll
                for (int jj = 0; jj < 4; jj++)
                    acc[ii][jj] += aa[ii] * bb[jj] + vvv[ii] * rv[3 + jj - ii];
        }

        // mask, scale, online softmax update
#pragma unroll
        for (int ii = 0; ii < 4; ii++) {
            int gi = i0 + iI + ii;
            float s4[4];
            float rowmax = -INFINITY;
#pragma unroll
            for (int jj = 0; jj < 4; jj++) {
                int gj = j0 + jJ + jj;
                float sc = acc[ii][jj] * 0.125f;
                if (gj > TAU_ + gi) sc = -1e30f;
                s4[jj] = sc;
                rowmax = fmaxf(rowmax, sc);
            }
#pragma unroll
            for (int off = 8; off; off >>= 1)
                rowmax = fmaxf(rowmax, __shfl_xor_sync(0xffffffffu, rowmax, off));
            float mnew = fmaxf(m[ii], rowmax);
            float corr = __expf(m[ii] - mnew);
            m[ii] = mnew;
            float ps = 0.f;
#pragma unroll
            for (int jj = 0; jj < 4; jj++) {
                float p = __expf(s4[jj] - mnew);
                sp[(iI + ii) * ATP + jJ + jj] = p;
                ps += p;
            }
#pragma unroll
            for (int off = 8; off; off >>= 1)
                ps += __shfl_xor_sync(0xffffffffu, ps, off);
            lsum[ii] = lsum[ii] * corr + ps;
#pragma unroll
            for (int c = 0; c < 4; c++) o[ii][c] *= corr;
        }
        __syncthreads();
        // O += P @ V   (each thread: rows iI..iI+3, cols tx*4..tx*4+3)
#pragma unroll 8
        for (int j = 0; j < 64; j++) {
            float4 vv = *(const float4*)(sv + j * ATP + tx * 4);
#pragma unroll
            for (int ii = 0; ii < 4; ii++) {
                float p = sp[(iI + ii) * ATP + j];
                o[ii][0] += p * vv.x; o[ii][1] += p * vv.y;
                o[ii][2] += p * vv.z; o[ii][3] += p * vv.w;
            }
        }
    }

#pragma unroll
    for (int ii = 0; ii < 4; ii++) {
        float inv = 1.0f / lsum[ii];
        float4 r4 = make_float4(o[ii][0] * inv, o[ii][1] * inv,
                                o[ii][2] * inv, o[ii][3] * inv);
        *(float4*)(g_attn + ((size_t)(b * T_ + i0 + iI + ii)) * DM_ + h * 64 + tx * 4) = r4;
    }
}

// ---------------- host launcher ---------------------------------------------
extern "C" void kernel_launch(void* const* d_in, const int* in_sizes, int n_in,
                              void* d_out, int out_size) {
    const float* inputs = (const float*)d_in[0];
    const float* memory = (const float*)d_in[1];
    const float* w_qkv  = (const float*)d_in[2];
    const float* w_pos  = (const float*)d_in[3];
    const float* w_out  = (const float*)d_in[4];
    const float* uvar   = (const float*)d_in[5];
    const float* vvar   = (const float*)d_in[6];
    const float* gamma  = (const float*)d_in[7];
    const float* beta   = (const float*)d_in[8];
    float* out = (float*)d_out;

    float *xln, *qkv, *phi, *R, *attn;
    cudaGetSymbolAddress((void**)&xln,  g_xln);
    cudaGetSymbolAddress((void**)&qkv,  g_qkv);
    cudaGetSymbolAddress((void**)&phi,  g_phi);
    cudaGetSymbolAddress((void**)&R,    g_R);
    cudaGetSymbolAddress((void**)&attn, g_attn);

    cudaFuncSetAttribute(attn_kernel,
                         cudaFuncAttributeMaxDynamicSharedMemorySize, ATT_SMEM);

    // 1) LayerNorm + concat
    ln_kernel<<<B_ * L_, 256>>>(inputs, memory, gamma, beta);
    // 2) positional features
    phi_kernel<<<L_, 256>>>();
    // 3) QKV = xln @ w_qkv^T   [4096 x 3072 x 1024]
    gemm_nt<<<dim3(3072 / 128, (B_ * L_) / 128), 256>>>(xln, w_qkv, qkv,
                                                        B_ * L_, 3 * DM_, DM_);
    // 4) R = phi @ w_pos^T     [1024 x 1024 x 1024]
    gemm_nt<<<dim3(DM_ / 128, L_ / 128), 256>>>(phi, w_pos, R, L_, DM_, DM_);
    // 5) fused relative attention
    attn_kernel<<<dim3(T_ / 64, B_ * H_), 256, ATT_SMEM>>>(uvar, vvar);
    // 6) out = attn @ w_out^T  [2048 x 1024 x 1024]
    gemm_nt<<<dim3(DM_ / 128, (B_ * T_) / 128), 256>>>(attn, w_out, out,
                                                       B_ * T_, DM_, DM_);
}

// round 6
// speedup vs baseline: 1.8081x; 1.8081x over previous
#include <cuda_runtime.h>
#include <math.h>
#include <stdint.h>

#define B_ 4
#define T_ 512
#define TAU_ 512
#define L_ 1024
#define DM_ 1024
#define H_ 16
#define D_ 64

// ---------------- scratch (device globals; no allocations allowed) ----------
__device__ float g_xln[B_ * L_ * DM_];        // 16 MB  LN(concat(mem, inp))
__device__ float g_qkv[B_ * L_ * 3 * DM_];    // 48 MB  [B,L,3072]
__device__ float g_phi[L_ * DM_];             //  4 MB
__device__ float g_R[L_ * DM_];               //  4 MB  [L, H*D]
__device__ float g_attn[B_ * T_ * DM_];       //  8 MB  [B,T,H*D]

// ---------------- LayerNorm over concat(memory, inputs) ---------------------
__global__ __launch_bounds__(256) void ln_kernel(const float* __restrict__ inputs,
                          const float* __restrict__ memory,
                          const float* __restrict__ gamma,
                          const float* __restrict__ beta) {
    int row = blockIdx.x;                 // 0..B*L-1
    int b = row >> 10, l = row & 1023;
    const float* src = (l < TAU_) ? memory + ((size_t)b * TAU_ + l) * DM_
                                  : inputs + ((size_t)b * T_ + (l - TAU_)) * DM_;
    int tid = threadIdx.x;                // 256 threads, 4 floats each
    float4 x = ((const float4*)src)[tid];
    float s  = x.x + x.y + x.z + x.w;
    float ss = x.x * x.x + x.y * x.y + x.z * x.z + x.w * x.w;
#pragma unroll
    for (int off = 16; off; off >>= 1) {
        s  += __shfl_xor_sync(0xffffffffu, s, off);
        ss += __shfl_xor_sync(0xffffffffu, ss, off);
    }
    __shared__ float red[16];
    int wid = tid >> 5, lane = tid & 31;
    if (lane == 0) { red[wid] = s; red[8 + wid] = ss; }
    __syncthreads();
    float ts = 0.f, tss = 0.f;
#pragma unroll
    for (int i = 0; i < 8; i++) { ts += red[i]; tss += red[8 + i]; }
    float mu   = ts * (1.0f / DM_);
    float var  = tss * (1.0f / DM_) - mu * mu;
    float rstd = rsqrtf(var + 1e-5f);
    float4 g  = ((const float4*)gamma)[tid];
    float4 bb = ((const float4*)beta)[tid];
    float4 o;
    o.x = (x.x - mu) * rstd * g.x + bb.x;
    o.y = (x.y - mu) * rstd * g.y + bb.y;
    o.z = (x.z - mu) * rstd * g.z + bb.z;
    o.w = (x.w - mu) * rstd * g.w + bb.w;
    ((float4*)(g_xln + (size_t)row * DM_))[tid] = o;
}

// ---------------- positional features phi[l, :] ------------------------------
__global__ __launch_bounds__(256) void phi_kernel() {
    int l = blockIdx.x;
    float pos = (float)(L_ - 1 - l);
    for (int f = threadIdx.x; f < 512; f += blockDim.x) {
        float ex  = (float)(2 * f) / 1024.0f;
        float inv = powf(10000.0f, -ex);
        float a = pos * inv;
        float sn, cs;
        sincosf(a, &sn, &cs);
        g_phi[(size_t)l * DM_ + f]       = sn;
        g_phi[(size_t)l * DM_ + 512 + f] = cs;
    }
}

// ---------------- tf32 mma.sync GEMM: C[M,N] = A[M,K] @ B[N,K]^T -------------
// 128x128x32 CTA tile, 512 threads = 16 warps (4x4), warp tile 32x32.
// smem stride 36 words -> fragment LDS banks = (4r+c)%32, conflict-free.
#define GST 36

__device__ __forceinline__ uint32_t tf32_rna(float f) {
    uint32_t r;
    asm("cvt.rna.tf32.f32 %0, %1;" : "=r"(r) : "f"(f));
    return r;
}

__device__ __forceinline__ void mma_tf32(float& c0, float& c1, float& c2, float& c3,
                                         uint32_t a0, uint32_t a1, uint32_t a2, uint32_t a3,
                                         uint32_t b0, uint32_t b1) {
    asm volatile(
        "mma.sync.aligned.m16n8k8.row.col.f32.tf32.tf32.f32 "
        "{%0,%1,%2,%3},{%4,%5,%6,%7},{%8,%9},{%0,%1,%2,%3};"
        : "+f"(c0), "+f"(c1), "+f"(c2), "+f"(c3)
        : "r"(a0), "r"(a1), "r"(a2), "r"(a3), "r"(b0), "r"(b1));
}

__global__ __launch_bounds__(512, 1) void gemm_mma(const float* __restrict__ A,
                                                   const float* __restrict__ Bm,
                                                   float* __restrict__ C,
                                                   int M, int N, int K) {
    __shared__ uint32_t sA[128 * GST];
    __shared__ uint32_t sB[128 * GST];
    int tid = threadIdx.x;
    int wid = tid >> 5, lane = tid & 31;
    int warp_m = wid >> 2, warp_n = wid & 3;       // 4x4 warps
    int bm = blockIdx.y * 128, bn = blockIdx.x * 128;
    int lr  = tid >> 3;                            // 0..63
    int lc4 = tid & 7;                             // float4 index 0..7
    int qrow = lane >> 2, qcol = lane & 3;

    float c[2][4][4];
#pragma unroll
    for (int mt = 0; mt < 2; mt++)
#pragma unroll
        for (int nt = 0; nt < 4; nt++)
#pragma unroll
            for (int e = 0; e < 4; e++) c[mt][nt][e] = 0.f;

    float4 stA[2], stB[2];
    const float* Abase = A  + (size_t)bm * K + lc4 * 4;
    const float* Bbase = Bm + (size_t)bn * K + lc4 * 4;

    // load chunk 0
#pragma unroll
    for (int p = 0; p < 2; p++) {
        stA[p] = *(const float4*)(Abase + (size_t)(lr + p * 64) * K);
        stB[p] = *(const float4*)(Bbase + (size_t)(lr + p * 64) * K);
    }
#pragma unroll
    for (int p = 0; p < 2; p++) {
        int off = (lr + p * 64) * GST + lc4 * 4;
        uint4 ta = make_uint4(tf32_rna(stA[p].x), tf32_rna(stA[p].y),
                              tf32_rna(stA[p].z), tf32_rna(stA[p].w));
        uint4 tb = make_uint4(tf32_rna(stB[p].x), tf32_rna(stB[p].y),
                              tf32_rna(stB[p].z), tf32_rna(stB[p].w));
        *(uint4*)(sA + off) = ta;
        *(uint4*)(sB + off) = tb;
    }
    __syncthreads();

    const int NC = K / 32;
    for (int kc = 0; kc < NC; kc++) {
        if (kc + 1 < NC) {
            int k0 = (kc + 1) * 32;
#pragma unroll
            for (int p = 0; p < 2; p++) {
                stA[p] = *(const float4*)(Abase + (size_t)(lr + p * 64) * K + k0);
                stB[p] = *(const float4*)(Bbase + (size_t)(lr + p * 64) * K + k0);
            }
        }
#pragma unroll
        for (int ks = 0; ks < 4; ks++) {
            int kk = ks * 8;
            uint32_t af[2][4], bf[4][2];
#pragma unroll
            for (int mt = 0; mt < 2; mt++) {
                int r = warp_m * 32 + mt * 16 + qrow;
                af[mt][0] = sA[r * GST + kk + qcol];
                af[mt][1] = sA[(r + 8) * GST + kk + qcol];
                af[mt][2] = sA[r * GST + kk + qcol + 4];
                af[mt][3] = sA[(r + 8) * GST + kk + qcol + 4];
            }
#pragma unroll
            for (int nt = 0; nt < 4; nt++) {
                int rn = warp_n * 32 + nt * 8 + qrow;
                bf[nt][0] = sB[rn * GST + kk + qcol];
                bf[nt][1] = sB[rn * GST + kk + qcol + 4];
            }
#pragma unroll
            for (int mt = 0; mt < 2; mt++)
#pragma unroll
                for (int nt = 0; nt < 4; nt++)
                    mma_tf32(c[mt][nt][0], c[mt][nt][1], c[mt][nt][2], c[mt][nt][3],
                             af[mt][0], af[mt][1], af[mt][2], af[mt][3],
                             bf[nt][0], bf[nt][1]);
        }
        __syncthreads();
        if (kc + 1 < NC) {
#pragma unroll
            for (int p = 0; p < 2; p++) {
                int off = (lr + p * 64) * GST + lc4 * 4;
                uint4 ta = make_uint4(tf32_rna(stA[p].x), tf32_rna(stA[p].y),
                                      tf32_rna(stA[p].z), tf32_rna(stA[p].w));
                uint4 tb = make_uint4(tf32_rna(stB[p].x), tf32_rna(stB[p].y),
                                      tf32_rna(stB[p].z), tf32_rna(stB[p].w));
                *(uint4*)(sA + off) = ta;
                *(uint4*)(sB + off) = tb;
            }
            __syncthreads();
        }
    }

    // epilogue: c0 at (qrow, 2*qcol), c1 +1 col, c2/c3 at row+8
#pragma unroll
    for (int mt = 0; mt < 2; mt++) {
        int row = bm + warp_m * 32 + mt * 16 + qrow;
#pragma unroll
        for (int nt = 0; nt < 4; nt++) {
            int col = bn + warp_n * 32 + nt * 8 + 2 * qcol;
            *(float2*)(C + (size_t)row * N + col) = make_float2(c[mt][nt][0], c[mt][nt][1]);
            *(float2*)(C + (size_t)(row + 8) * N + col) = make_float2(c[mt][nt][2], c[mt][nt][3]);
        }
    }
}

// ---------------- fused flash attention with relative shift -----------------
// grid: (T/64, B*H), 256 threads. Each block: 64 query rows of one (b,h).
// rel_shift(P)[i,j] = P[i, j + T - 1 - i] for all unmasked (j <= TAU + i).
#define ATP 68
#define ATPR 132
#define ATT_SMEM ((64 * ATP * 5 + 64 * ATPR) * 4)

__global__ __launch_bounds__(256) void attn_kernel(const float* __restrict__ uvar,
                            const float* __restrict__ vvar) {
    extern __shared__ float sm[];
    float* squ = sm;                    // [64 d][ATP]  q + u   (d-major)
    float* sqv = squ + 64 * ATP;        // [64 d][ATP]  q + v
    float* sk  = sqv + 64 * ATP;        // [64 d][ATP]  k tile
    float* sr  = sk + 64 * ATP;         // [64 d][ATPR] 128 R rows
    float* sv  = sr + 64 * ATPR;        // [64 j][ATP]  v tile (j-major)
    float* sp  = sv + 64 * ATP;         // [64 i][ATP]  probs

    int i0 = blockIdx.x * 64;
    int b  = blockIdx.y >> 4;
    int h  = blockIdx.y & 15;
    int tid = threadIdx.x;
    int tx = tid & 15, ty = tid >> 4;
    int iI = ty * 4, jJ = tx * 4;

    // load q tiles once (row = TAU + i0 + i of full sequence)
    for (int e = tid; e < 64 * 64; e += 256) {
        int i = e >> 6, d = e & 63;
        float q = g_qkv[((size_t)(b * L_ + TAU_ + i0 + i)) * 3072 + h * 64 + d];
        squ[d * ATP + i] = q + uvar[h * 64 + d];
        sqv[d * ATP + i] = q + vvar[h * 64 + d];
    }

    float m[4], lsum[4], o[4][4];
#pragma unroll
    for (int ii = 0; ii < 4; ii++) {
        m[ii] = -INFINITY; lsum[ii] = 0.f;
#pragma unroll
        for (int c = 0; c < 4; c++) o[ii][c] = 0.f;
    }

    int ntiles = (TAU_ + i0 + 63) / 64 + 1;   // causal: j <= TAU + i
    for (int jt = 0; jt < ntiles; jt++) {
        int j0 = jt * 64;
        __syncthreads();
        // load K and V tiles
        for (int e = tid; e < 4096; e += 256) {
            int j = e >> 6, d = e & 63;
            size_t base = ((size_t)(b * L_ + j0 + j)) * 3072 + h * 64 + d;
            sk[d * ATP + j] = g_qkv[base + 1024];
            sv[j * ATP + d] = g_qkv[base + 2048];
        }
        // load 128-row R band: rows [rbase, rbase+127]
        int rbase = j0 + T_ - 64 - i0;
        for (int e = tid; e < 8192; e += 256) {
            int r = e >> 6, d = e & 63;
            int rr = rbase + r; rr = rr > (L_ - 1) ? (L_ - 1) : rr;
            sr[d * ATPR + r] = g_R[(size_t)rr * DM_ + h * 64 + d];
        }
        __syncthreads();

        float acc[4][4];
#pragma unroll
        for (int ii = 0; ii < 4; ii++)
#pragma unroll
            for (int jj = 0; jj < 4; jj++) acc[ii][jj] = 0.f;
        int rb = jJ - iI + 60;   // sr offset so rv[3 + jj - ii] is the shifted R row
#pragma unroll 4
        for (int dd = 0; dd < 64; dd++) {
            float4 a  = *(const float4*)(squ + dd * ATP + iI);
            float4 av = *(const float4*)(sqv + dd * ATP + iI);
            float4 bk = *(const float4*)(sk  + dd * ATP + jJ);
            float rv[7];
#pragma unroll
            for (int x = 0; x < 7; x++) rv[x] = sr[dd * ATPR + rb + x];
            float aa[4] = {a.x, a.y, a.z, a.w};
            float vvv[4] = {av.x, av.y, av.z, av.w};
            float bb[4] = {bk.x, bk.y, bk.z, bk.w};
#pragma unroll
            for (int ii = 0; ii < 4; ii++)
#pragma unroll
                for (int jj = 0; jj < 4; jj++)
                    acc[ii][jj] += aa[ii] * bb[jj] + vvv[ii] * rv[3 + jj - ii];
        }

        // mask, scale, online softmax update
#pragma unroll
        for (int ii = 0; ii < 4; ii++) {
            int gi = i0 + iI + ii;
            float s4[4];
            float rowmax = -INFINITY;
#pragma unroll
            for (int jj = 0; jj < 4; jj++) {
                int gj = j0 + jJ + jj;
                float sc = acc[ii][jj] * 0.125f;
                if (gj > TAU_ + gi) sc = -1e30f;
                s4[jj] = sc;
                rowmax = fmaxf(rowmax, sc);
            }
#pragma unroll
            for (int off = 8; off; off >>= 1)
                rowmax = fmaxf(rowmax, __shfl_xor_sync(0xffffffffu, rowmax, off));
            float mnew = fmaxf(m[ii], rowmax);
            float corr = __expf(m[ii] - mnew);
            m[ii] = mnew;
            float ps = 0.f;
#pragma unroll
            for (int jj = 0; jj < 4; jj++) {
                float p = __expf(s4[jj] - mnew);
                sp[(iI + ii) * ATP + jJ + jj] = p;
                ps += p;
            }
#pragma unroll
            for (int off = 8; off; off >>= 1)
                ps += __shfl_xor_sync(0xffffffffu, ps, off);
            lsum[ii] = lsum[ii] * corr + ps;
#pragma unroll
            for (int c = 0; c < 4; c++) o[ii][c] *= corr;
        }
        __syncthreads();
        // O += P @ V   (each thread: rows iI..iI+3, cols tx*4..tx*4+3)
#pragma unroll 8
        for (int j = 0; j < 64; j++) {
            float4 vv = *(const float4*)(sv + j * ATP + tx * 4);
#pragma unroll
            for (int ii = 0; ii < 4; ii++) {
                float p = sp[(iI + ii) * ATP + j];
                o[ii][0] += p * vv.x; o[ii][1] += p * vv.y;
                o[ii][2] += p * vv.z; o[ii][3] += p * vv.w;
            }
        }
    }

#pragma unroll
    for (int ii = 0; ii < 4; ii++) {
        float inv = 1.0f / lsum[ii];
        float4 r4 = make_float4(o[ii][0] * inv, o[ii][1] * inv,
                                o[ii][2] * inv, o[ii][3] * inv);
        *(float4*)(g_attn + ((size_t)(b * T_ + i0 + iI + ii)) * DM_ + h * 64 + tx * 4) = r4;
    }
}

// ---------------- host launcher ---------------------------------------------
extern "C" void kernel_launch(void* const* d_in, const int* in_sizes, int n_in,
                              void* d_out, int out_size) {
    const float* inputs = (const float*)d_in[0];
    const float* memory = (const float*)d_in[1];
    const float* w_qkv  = (const float*)d_in[2];
    const float* w_pos  = (const float*)d_in[3];
    const float* w_out  = (const float*)d_in[4];
    const float* uvar   = (const float*)d_in[5];
    const float* vvar   = (const float*)d_in[6];
    const float* gamma  = (const float*)d_in[7];
    const float* beta   = (const float*)d_in[8];
    float* out = (float*)d_out;

    float *xln, *qkv, *phi, *R, *attn;
    cudaGetSymbolAddress((void**)&xln,  g_xln);
    cudaGetSymbolAddress((void**)&qkv,  g_qkv);
    cudaGetSymbolAddress((void**)&phi,  g_phi);
    cudaGetSymbolAddress((void**)&R,    g_R);
    cudaGetSymbolAddress((void**)&attn, g_attn);

    cudaFuncSetAttribute(attn_kernel,
                         cudaFuncAttributeMaxDynamicSharedMemorySize, ATT_SMEM);

    // 1) LayerNorm + concat
    ln_kernel<<<B_ * L_, 256>>>(inputs, memory, gamma, beta);
    // 2) positional features
    phi_kernel<<<L_, 256>>>();
    // 3) QKV = xln @ w_qkv^T   [4096 x 3072 x 1024]
    gemm_mma<<<dim3(3072 / 128, (B_ * L_) / 128), 512>>>(
        xln, w_qkv, qkv, B_ * L_, 3 * DM_, DM_);
    // 4) R = phi @ w_pos^T     [1024 x 1024 x 1024]
    gemm_mma<<<dim3(DM_ / 128, L_ / 128), 512>>>(
        phi, w_pos, R, L_, DM_, DM_);
    // 5) fused relative attention
    attn_kernel<<<dim3(T_ / 64, B_ * H_), 256, ATT_SMEM>>>(uvar, vvar);
    // 6) out = attn @ w_out^T  [2048 x 1024 x 1024]
    gemm_mma<<<dim3(DM_ / 128, (B_ * T_) / 128), 512>>>(
        attn, w_out, out, B_ * T_, DM_, DM_);
}

// round 7
// speedup vs baseline: 2.4817x; 1.3726x over previous
#include <cuda_runtime.h>
#include <math.h>
#include <stdint.h>

#define B_ 4
#define T_ 512
#define TAU_ 512
#define L_ 1024
#define DM_ 1024
#define H_ 16
#define D_ 64

// ---------------- scratch (device globals; no allocations allowed) ----------
__device__ float g_xln[B_ * L_ * DM_];        // 16 MB  LN(concat(mem, inp))
__device__ float g_qkv[B_ * L_ * 3 * DM_];    // 48 MB  [B,L,3072]
__device__ float g_phi[L_ * DM_];             //  4 MB
__device__ float g_R[L_ * DM_];               //  4 MB  [L, H*D]
__device__ float g_attn[B_ * T_ * DM_];       //  8 MB  [B,T,H*D]

__device__ __forceinline__ uint32_t tf32_rna(float f) {
    uint32_t r;
    asm("cvt.rna.tf32.f32 %0, %1;" : "=r"(r) : "f"(f));
    return r;
}
__device__ __forceinline__ float tf32f(float f) {
    return __uint_as_float(tf32_rna(f));
}
__device__ __forceinline__ void mma_tf32(float& c0, float& c1, float& c2, float& c3,
                                         uint32_t a0, uint32_t a1, uint32_t a2, uint32_t a3,
                                         uint32_t b0, uint32_t b1) {
    asm volatile(
        "mma.sync.aligned.m16n8k8.row.col.f32.tf32.tf32.f32 "
        "{%0,%1,%2,%3},{%4,%5,%6,%7},{%8,%9},{%0,%1,%2,%3};"
        : "+f"(c0), "+f"(c1), "+f"(c2), "+f"(c3)
        : "r"(a0), "r"(a1), "r"(a2), "r"(a3), "r"(b0), "r"(b1));
}

// ---------------- LayerNorm over concat(memory, inputs) ---------------------
__global__ __launch_bounds__(256) void ln_kernel(const float* __restrict__ inputs,
                          const float* __restrict__ memory,
                          const float* __restrict__ gamma,
                          const float* __restrict__ beta) {
    int row = blockIdx.x;
    int b = row >> 10, l = row & 1023;
    const float* src = (l < TAU_) ? memory + ((size_t)b * TAU_ + l) * DM_
                                  : inputs + ((size_t)b * T_ + (l - TAU_)) * DM_;
    int tid = threadIdx.x;
    float4 x = ((const float4*)src)[tid];
    float s  = x.x + x.y + x.z + x.w;
    float ss = x.x * x.x + x.y * x.y + x.z * x.z + x.w * x.w;
#pragma unroll
    for (int off = 16; off; off >>= 1) {
        s  += __shfl_xor_sync(0xffffffffu, s, off);
        ss += __shfl_xor_sync(0xffffffffu, ss, off);
    }
    __shared__ float red[16];
    int wid = tid >> 5, lane = tid & 31;
    if (lane == 0) { red[wid] = s; red[8 + wid] = ss; }
    __syncthreads();
    float ts = 0.f, tss = 0.f;
#pragma unroll
    for (int i = 0; i < 8; i++) { ts += red[i]; tss += red[8 + i]; }
    float mu   = ts * (1.0f / DM_);
    float var  = tss * (1.0f / DM_) - mu * mu;
    float rstd = rsqrtf(var + 1e-5f);
    float4 g  = ((const float4*)gamma)[tid];
    float4 bb = ((const float4*)beta)[tid];
    float4 o;
    o.x = (x.x - mu) * rstd * g.x + bb.x;
    o.y = (x.y - mu) * rstd * g.y + bb.y;
    o.z = (x.z - mu) * rstd * g.z + bb.z;
    o.w = (x.w - mu) * rstd * g.w + bb.w;
    ((float4*)(g_xln + (size_t)row * DM_))[tid] = o;
}

// ---------------- positional features phi[l, :] ------------------------------
__global__ __launch_bounds__(256) void phi_kernel() {
    int l = blockIdx.x;
    float pos = (float)(L_ - 1 - l);
    for (int f = threadIdx.x; f < 512; f += blockDim.x) {
        float ex  = (float)(2 * f) / 1024.0f;
        float inv = powf(10000.0f, -ex);
        float a = pos * inv;
        float sn, cs;
        sincosf(a, &sn, &cs);
        g_phi[(size_t)l * DM_ + f]       = sn;
        g_phi[(size_t)l * DM_ + 512 + f] = cs;
    }
}

// ---------------- tf32 mma.sync GEMM: C[M,N] = A[M,K] @ B[N,K]^T -------------
#define GST 36

__global__ __launch_bounds__(512, 1) void gemm_mma(const float* __restrict__ A,
                                                   const float* __restrict__ Bm,
                                                   float* __restrict__ C,
                                                   int M, int N, int K) {
    __shared__ uint32_t sA[128 * GST];
    __shared__ uint32_t sB[128 * GST];
    int tid = threadIdx.x;
    int wid = tid >> 5, lane = tid & 31;
    int warp_m = wid >> 2, warp_n = wid & 3;
    int bm = blockIdx.y * 128, bn = blockIdx.x * 128;
    int lr  = tid >> 3;
    int lc4 = tid & 7;
    int qrow = lane >> 2, qcol = lane & 3;

    float c[2][4][4];
#pragma unroll
    for (int mt = 0; mt < 2; mt++)
#pragma unroll
        for (int nt = 0; nt < 4; nt++)
#pragma unroll
            for (int e = 0; e < 4; e++) c[mt][nt][e] = 0.f;

    float4 stA[2], stB[2];
    const float* Abase = A  + (size_t)bm * K + lc4 * 4;
    const float* Bbase = Bm + (size_t)bn * K + lc4 * 4;

#pragma unroll
    for (int p = 0; p < 2; p++) {
        stA[p] = *(const float4*)(Abase + (size_t)(lr + p * 64) * K);
        stB[p] = *(const float4*)(Bbase + (size_t)(lr + p * 64) * K);
    }
#pragma unroll
    for (int p = 0; p < 2; p++) {
        int off = (lr + p * 64) * GST + lc4 * 4;
        uint4 ta = make_uint4(tf32_rna(stA[p].x), tf32_rna(stA[p].y),
                              tf32_rna(stA[p].z), tf32_rna(stA[p].w));
        uint4 tb = make_uint4(tf32_rna(stB[p].x), tf32_rna(stB[p].y),
                              tf32_rna(stB[p].z), tf32_rna(stB[p].w));
        *(uint4*)(sA + off) = ta;
        *(uint4*)(sB + off) = tb;
    }
    __syncthreads();

    const int NC = K / 32;
    for (int kc = 0; kc < NC; kc++) {
        if (kc + 1 < NC) {
            int k0 = (kc + 1) * 32;
#pragma unroll
            for (int p = 0; p < 2; p++) {
                stA[p] = *(const float4*)(Abase + (size_t)(lr + p * 64) * K + k0);
                stB[p] = *(const float4*)(Bbase + (size_t)(lr + p * 64) * K + k0);
            }
        }
#pragma unroll
        for (int ks = 0; ks < 4; ks++) {
            int kk = ks * 8;
            uint32_t af[2][4], bf[4][2];
#pragma unroll
            for (int mt = 0; mt < 2; mt++) {
                int r = warp_m * 32 + mt * 16 + qrow;
                af[mt][0] = sA[r * GST + kk + qcol];
                af[mt][1] = sA[(r + 8) * GST + kk + qcol];
                af[mt][2] = sA[r * GST + kk + qcol + 4];
                af[mt][3] = sA[(r + 8) * GST + kk + qcol + 4];
            }
#pragma unroll
            for (int nt = 0; nt < 4; nt++) {
                int rn = warp_n * 32 + nt * 8 + qrow;
                bf[nt][0] = sB[rn * GST + kk + qcol];
                bf[nt][1] = sB[rn * GST + kk + qcol + 4];
            }
#pragma unroll
            for (int mt = 0; mt < 2; mt++)
#pragma unroll
                for (int nt = 0; nt < 4; nt++)
                    mma_tf32(c[mt][nt][0], c[mt][nt][1], c[mt][nt][2], c[mt][nt][3],
                             af[mt][0], af[mt][1], af[mt][2], af[mt][3],
                             bf[nt][0], bf[nt][1]);
        }
        __syncthreads();
        if (kc + 1 < NC) {
#pragma unroll
            for (int p = 0; p < 2; p++) {
                int off = (lr + p * 64) * GST + lc4 * 4;
                uint4 ta = make_uint4(tf32_rna(stA[p].x), tf32_rna(stA[p].y),
                                      tf32_rna(stA[p].z), tf32_rna(stA[p].w));
                uint4 tb = make_uint4(tf32_rna(stB[p].x), tf32_rna(stB[p].y),
                                      tf32_rna(stB[p].z), tf32_rna(stB[p].w));
                *(uint4*)(sA + off) = ta;
                *(uint4*)(sB + off) = tb;
            }
            __syncthreads();
        }
    }

#pragma unroll
    for (int mt = 0; mt < 2; mt++) {
        int row = bm + warp_m * 32 + mt * 16 + qrow;
#pragma unroll
        for (int nt = 0; nt < 4; nt++) {
            int col = bn + warp_n * 32 + nt * 8 + 2 * qcol;
            *(float2*)(C + (size_t)row * N + col) = make_float2(c[mt][nt][0], c[mt][nt][1]);
            *(float2*)(C + (size_t)(row + 8) * N + col) = make_float2(c[mt][nt][2], c[mt][nt][3]);
        }
    }
}

// ---------------- mma-based fused relative flash attention -------------------
// Block: 64 query rows of one (b,h); 256 threads = 8 warps (4m x 2n).
// rel_shift(P)[i,j] = P[i, j+T-1-i] for unmasked (j <= TAU+i).
// E-band ring: E[i, p] for 128 R rows; rbase advances 64/tile (rbase % 64 == 0),
// so each tile computes exactly one new 64-col half (two at jt=0).
#define AW 68
#define AEW 132
// floats: 7*64*AW + 64*AEW + 192
#define ATT_SMEM ((7 * 64 * AW + 64 * AEW + 192) * 4)

__global__ __launch_bounds__(256) void attn_mma(const float* __restrict__ uvar,
                                                const float* __restrict__ vvar) {
    extern __shared__ float sm[];
    float* sQU = sm;                 // [64][AW] tf32 q+u
    float* sQV = sQU + 64 * AW;      // [64][AW] tf32 q+v
    float* sK  = sQV + 64 * AW;      // [64 j][AW] tf32
    float* sV  = sK  + 64 * AW;      // [64 d][AW j] tf32 (transposed)
    float* sR  = sV  + 64 * AW;      // [64][AW] tf32 current R batch
    float* sS  = sR  + 64 * AW;      // [64][AW] fp32 scores
    float* sP  = sS  + 64 * AW;      // [64][AW] tf32 probs
    float* sE  = sP  + 64 * AW;      // [64][AEW] fp32 E ring (128 cols)
    float* sm_m = sE + 64 * AEW;     // [64]
    float* sm_l = sm_m + 64;         // [64]
    float* sm_c = sm_l + 64;         // [64]

    const uint32_t* uQU = (const uint32_t*)sQU;
    const uint32_t* uQV = (const uint32_t*)sQV;
    const uint32_t* uK  = (const uint32_t*)sK;
    const uint32_t* uV  = (const uint32_t*)sV;
    const uint32_t* uR  = (const uint32_t*)sR;
    const uint32_t* uP  = (const uint32_t*)sP;

    int i0 = blockIdx.x * 64;
    int b  = blockIdx.y >> 4;
    int h  = blockIdx.y & 15;
    int tid = threadIdx.x;
    int wid = tid >> 5, lane = tid & 31;
    int wm = wid >> 1, wn = wid & 1;
    int qrow = lane >> 2, qcol = lane & 3;

    // load q tiles, add u/v, convert tf32
    for (int e = tid; e < 4096; e += 256) {
        int i = e >> 6, d = e & 63;
        float q = g_qkv[((size_t)(b * L_ + TAU_ + i0 + i)) * 3072 + h * 64 + d];
        sQU[i * AW + d] = tf32f(q + uvar[h * 64 + d]);
        sQV[i * AW + d] = tf32f(q + vvar[h * 64 + d]);
    }
    if (tid < 64) { sm_m[tid] = -INFINITY; sm_l[tid] = 0.f; }

    float o[4][4];
#pragma unroll
    for (int nt = 0; nt < 4; nt++)
#pragma unroll
        for (int e = 0; e < 4; e++) o[nt][e] = 0.f;

    int ntiles = (TAU_ + i0 + 63) / 64 + 1;
    int rnext = 448 - i0;                 // next R row batch start (== rbase(0))

    for (int jt = 0; jt < ntiles; jt++) {
        int j0 = jt * 64;
        int rband = j0 + 448 - i0;        // rbase(jt)
        __syncthreads();                  // prev tile's mma done with sK/sV/sP

        // load K, V tiles
        for (int e = tid; e < 4096; e += 256) {
            int j = e >> 6, d = e & 63;
            size_t base = ((size_t)(b * L_ + j0 + j)) * 3072 + h * 64 + d;
            sK[j * AW + d] = tf32f(g_qkv[base + 1024]);
            sV[d * AW + j] = tf32f(g_qkv[base + 2048]);
        }

        // R batches: load 64 rows, compute E half via mma
        while (rnext < rband + 128) {
            for (int e = tid; e < 4096; e += 256) {
                int r = e >> 6, d = e & 63;
                int rr = rnext + r; rr = rr > (L_ - 1) ? (L_ - 1) : rr;
                sR[r * AW + d] = tf32f(g_R[(size_t)rr * DM_ + h * 64 + d]);
            }
            __syncthreads();              // sR (+ sQV first time) visible
            int hf = (rnext >> 6) & 1;
            float ce[4][4];
#pragma unroll
            for (int nt = 0; nt < 4; nt++)
#pragma unroll
                for (int e = 0; e < 4; e++) ce[nt][e] = 0.f;
#pragma unroll
            for (int ks = 0; ks < 8; ks++) {
                int kk = ks * 8;
                int r = wm * 16 + qrow;
                uint32_t a0 = uQV[r * AW + kk + qcol];
                uint32_t a1 = uQV[(r + 8) * AW + kk + qcol];
                uint32_t a2 = uQV[r * AW + kk + qcol + 4];
                uint32_t a3 = uQV[(r + 8) * AW + kk + qcol + 4];
#pragma unroll
                for (int nt = 0; nt < 4; nt++) {
                    int rn = wn * 32 + nt * 8 + qrow;
                    uint32_t b0 = uR[rn * AW + kk + qcol];
                    uint32_t b1 = uR[rn * AW + kk + qcol + 4];
                    mma_tf32(ce[nt][0], ce[nt][1], ce[nt][2], ce[nt][3],
                             a0, a1, a2, a3, b0, b1);
                }
            }
            {
                int row = wm * 16 + qrow;
#pragma unroll
                for (int nt = 0; nt < 4; nt++) {
                    int col = hf * 64 + wn * 32 + nt * 8 + 2 * qcol;
                    sE[row * AEW + col]     = ce[nt][0];
                    sE[row * AEW + col + 1] = ce[nt][1];
                    sE[(row + 8) * AEW + col]     = ce[nt][2];
                    sE[(row + 8) * AEW + col + 1] = ce[nt][3];
                }
            }
            __syncthreads();              // E visible; sR free for next batch
            rnext += 64;
        }

        // S = QU @ K^T  -> sS
        {
            float cs[4][4];
#pragma unroll
            for (int nt = 0; nt < 4; nt++)
#pragma unroll
                for (int e = 0; e < 4; e++) cs[nt][e] = 0.f;
#pragma unroll
            for (int ks = 0; ks < 8; ks++) {
                int kk = ks * 8;
                int r = wm * 16 + qrow;
                uint32_t a0 = uQU[r * AW + kk + qcol];
                uint32_t a1 = uQU[(r + 8) * AW + kk + qcol];
                uint32_t a2 = uQU[r * AW + kk + qcol + 4];
                uint32_t a3 = uQU[(r + 8) * AW + kk + qcol + 4];
#pragma unroll
                for (int nt = 0; nt < 4; nt++) {
                    int rn = wn * 32 + nt * 8 + qrow;
                    uint32_t b0 = uK[rn * AW + kk + qcol];
                    uint32_t b1 = uK[rn * AW + kk + qcol + 4];
                    mma_tf32(cs[nt][0], cs[nt][1], cs[nt][2], cs[nt][3],
                             a0, a1, a2, a3, b0, b1);
                }
            }
            int row = wm * 16 + qrow;
#pragma unroll
            for (int nt = 0; nt < 4; nt++) {
                int col = wn * 32 + nt * 8 + 2 * qcol;
                sS[row * AW + col]     = cs[nt][0];
                sS[row * AW + col + 1] = cs[nt][1];
                sS[(row + 8) * AW + col]     = cs[nt][2];
                sS[(row + 8) * AW + col + 1] = cs[nt][3];
            }
        }
        __syncthreads();

        // scalar: gather rel-shift, mask, online softmax -> sP (tf32), corr
        {
            int row = tid >> 2, cbase = (tid & 3) * 16;
            int gi = i0 + row;
            float oldm = sm_m[row];
            int sb = rband + 63 - row;
            float s16[16], mx = -INFINITY;
#pragma unroll
            for (int x = 0; x < 16; x++) {
                int jp = cbase + x;
                float s = (sS[row * AW + jp] + sE[row * AEW + ((sb + jp) & 127)]) * 0.125f;
                if (j0 + jp > TAU_ + gi) s = -1e30f;
                s16[x] = s;
                mx = fmaxf(mx, s);
            }
            mx = fmaxf(mx, __shfl_xor_sync(0xffffffffu, mx, 1));
            mx = fmaxf(mx, __shfl_xor_sync(0xffffffffu, mx, 2));
            float mnew = fmaxf(oldm, mx);
            float corr = __expf(oldm - mnew);
            float ps = 0.f;
#pragma unroll
            for (int x = 0; x < 16; x++) {
                float p = __expf(s16[x] - mnew);
                sP[row * AW + cbase + x] = tf32f(p);
                ps += p;
            }
            ps += __shfl_xor_sync(0xffffffffu, ps, 1);
            ps += __shfl_xor_sync(0xffffffffu, ps, 2);
            if ((tid & 3) == 0) {
                sm_m[row] = mnew;
                sm_l[row] = sm_l[row] * corr + ps;
                sm_c[row] = corr;
            }
        }
        __syncthreads();

        // O = O*corr + P @ V
        {
            float cr0 = sm_c[wm * 16 + qrow];
            float cr1 = sm_c[wm * 16 + qrow + 8];
#pragma unroll
            for (int nt = 0; nt < 4; nt++) {
                o[nt][0] *= cr0; o[nt][1] *= cr0;
                o[nt][2] *= cr1; o[nt][3] *= cr1;
            }
#pragma unroll
            for (int ks = 0; ks < 8; ks++) {
                int kk = ks * 8;
                int r = wm * 16 + qrow;
                uint32_t a0 = uP[r * AW + kk + qcol];
                uint32_t a1 = uP[(r + 8) * AW + kk + qcol];
                uint32_t a2 = uP[r * AW + kk + qcol + 4];
                uint32_t a3 = uP[(r + 8) * AW + kk + qcol + 4];
#pragma unroll
                for (int nt = 0; nt < 4; nt++) {
                    int rn = wn * 32 + nt * 8 + qrow;
                    uint32_t b0 = uV[rn * AW + kk + qcol];
                    uint32_t b1 = uV[rn * AW + kk + qcol + 4];
                    mma_tf32(o[nt][0], o[nt][1], o[nt][2], o[nt][3],
                             a0, a1, a2, a3, b0, b1);
                }
            }
        }
    }

    // write O / lsum
    {
        int row = wm * 16 + qrow;
        float inv0 = 1.0f / sm_l[row];
        float inv1 = 1.0f / sm_l[row + 8];
#pragma unroll
        for (int nt = 0; nt < 4; nt++) {
            int col = h * 64 + wn * 32 + nt * 8 + 2 * qcol;
            *(float2*)(g_attn + ((size_t)(b * T_ + i0 + row)) * DM_ + col) =
                make_float2(o[nt][0] * inv0, o[nt][1] * inv0);
            *(float2*)(g_attn + ((size_t)(b * T_ + i0 + row + 8)) * DM_ + col) =
                make_float2(o[nt][2] * inv1, o[nt][3] * inv1);
        }
    }
}

// ---------------- host launcher ---------------------------------------------
extern "C" void kernel_launch(void* const* d_in, const int* in_sizes, int n_in,
                              void* d_out, int out_size) {
    const float* inputs = (const float*)d_in[0];
    const float* memory = (const float*)d_in[1];
    const float* w_qkv  = (const float*)d_in[2];
    const float* w_pos  = (const float*)d_in[3];
    const float* w_out  = (const float*)d_in[4];
    const float* uvar   = (const float*)d_in[5];
    const float* vvar   = (const float*)d_in[6];
    const float* gamma  = (const float*)d_in[7];
    const float* beta   = (const float*)d_in[8];
    float* out = (float*)d_out;

    float *xln, *qkv, *phi, *R, *attn;
    cudaGetSymbolAddress((void**)&xln,  g_xln);
    cudaGetSymbolAddress((void**)&qkv,  g_qkv);
    cudaGetSymbolAddress((void**)&phi,  g_phi);
    cudaGetSymbolAddress((void**)&R,    g_R);
    cudaGetSymbolAddress((void**)&attn, g_attn);

    cudaFuncSetAttribute(attn_mma,
                         cudaFuncAttributeMaxDynamicSharedMemorySize, ATT_SMEM);

    // 1) LayerNorm + concat
    ln_kernel<<<B_ * L_, 256>>>(inputs, memory, gamma, beta);
    // 2) positional features
    phi_kernel<<<L_, 256>>>();
    // 3) QKV = xln @ w_qkv^T   [4096 x 3072 x 1024]
    gemm_mma<<<dim3(3072 / 128, (B_ * L_) / 128), 512>>>(
        xln, w_qkv, qkv, B_ * L_, 3 * DM_, DM_);
    // 4) R = phi @ w_pos^T     [1024 x 1024 x 1024]
    gemm_mma<<<dim3(DM_ / 128, L_ / 128), 512>>>(
        phi, w_pos, R, L_, DM_, DM_);
    // 5) fused relative attention (tensor-core)
    attn_mma<<<dim3(T_ / 64, B_ * H_), 256, ATT_SMEM>>>(uvar, vvar);
    // 6) out = attn @ w_out^T  [2048 x 1024 x 1024]
    gemm_mma<<<dim3(DM_ / 128, (B_ * T_) / 128), 512>>>(
        attn, w_out, out, B_ * T_, DM_, DM_);
}

// round 8
// speedup vs baseline: 2.8118x; 1.1330x over previous
#include <cuda_runtime.h>
#include <math.h>
#include <stdint.h>

#define B_ 4
#define T_ 512
#define TAU_ 512
#define L_ 1024
#define DM_ 1024
#define H_ 16
#define D_ 64

// ---------------- scratch (device globals; no allocations allowed) ----------
__device__ float g_xln[B_ * L_ * DM_];        // 16 MB  LN out (tf32-rounded)
__device__ float g_qkv[B_ * L_ * 3 * DM_];    // 48 MB  [B,L,3072]
__device__ float g_phi[L_ * DM_];             //  4 MB  (tf32-rounded)
__device__ float g_R[L_ * DM_];               //  4 MB  [L, H*D]
__device__ float g_attn[B_ * T_ * DM_];       //  8 MB  (tf32-rounded)
__device__ float g_wqkv[3 * DM_ * DM_];       // 12 MB  rounded weights
__device__ float g_wpos[DM_ * DM_];           //  4 MB
__device__ float g_wout[DM_ * DM_];           //  4 MB

__device__ __forceinline__ uint32_t tf32_rna(float f) {
    uint32_t r;
    asm("cvt.rna.tf32.f32 %0, %1;" : "=r"(r) : "f"(f));
    return r;
}
__device__ __forceinline__ float tf32f(float f) {
    return __uint_as_float(tf32_rna(f));
}
__device__ __forceinline__ uint32_t smem_u32(const void* p) {
    uint32_t a;
    asm("{ .reg .u64 t; cvta.to.shared.u64 t, %1; cvt.u32.u64 %0, t; }" : "=r"(a) : "l"(p));
    return a;
}
__device__ __forceinline__ void mma_tf32(float& c0, float& c1, float& c2, float& c3,
                                         uint32_t a0, uint32_t a1, uint32_t a2, uint32_t a3,
                                         uint32_t b0, uint32_t b1) {
    asm volatile(
        "mma.sync.aligned.m16n8k8.row.col.f32.tf32.tf32.f32 "
        "{%0,%1,%2,%3},{%4,%5,%6,%7},{%8,%9},{%0,%1,%2,%3};"
        : "+f"(c0), "+f"(c1), "+f"(c2), "+f"(c3)
        : "r"(a0), "r"(a1), "r"(a2), "r"(a3), "r"(b0), "r"(b1));
}
__device__ __forceinline__ void cp16(uint32_t dst, const void* src) {
    asm volatile("cp.async.cg.shared.global [%0], [%1], 16;" :: "r"(dst), "l"(src));
}
__device__ __forceinline__ void cp_commit() {
    asm volatile("cp.async.commit_group;" ::: "memory");
}
__device__ __forceinline__ void cp_wait2() {
    asm volatile("cp.async.wait_group 2;" ::: "memory");
}

// ---------------- round weights to tf32 --------------------------------------
__global__ __launch_bounds__(256) void round_tf32_kernel(const float* __restrict__ src,
                                                         float* __restrict__ dst, int n4) {
    int i = blockIdx.x * blockDim.x + threadIdx.x;
    if (i < n4) {
        float4 v = ((const float4*)src)[i];
        v.x = tf32f(v.x); v.y = tf32f(v.y); v.z = tf32f(v.z); v.w = tf32f(v.w);
        ((float4*)dst)[i] = v;
    }
}

// ---------------- LayerNorm over concat(memory, inputs), tf32 out ------------
__global__ __launch_bounds__(256) void ln_kernel(const float* __restrict__ inputs,
                          const float* __restrict__ memory,
                          const float* __restrict__ gamma,
                          const float* __restrict__ beta) {
    int row = blockIdx.x;
    int b = row >> 10, l = row & 1023;
    const float* src = (l < TAU_) ? memory + ((size_t)b * TAU_ + l) * DM_
                                  : inputs + ((size_t)b * T_ + (l - TAU_)) * DM_;
    int tid = threadIdx.x;
    float4 x = ((const float4*)src)[tid];
    float s  = x.x + x.y + x.z + x.w;
    float ss = x.x * x.x + x.y * x.y + x.z * x.z + x.w * x.w;
#pragma unroll
    for (int off = 16; off; off >>= 1) {
        s  += __shfl_xor_sync(0xffffffffu, s, off);
        ss += __shfl_xor_sync(0xffffffffu, ss, off);
    }
    __shared__ float red[16];
    int wid = tid >> 5, lane = tid & 31;
    if (lane == 0) { red[wid] = s; red[8 + wid] = ss; }
    __syncthreads();
    float ts = 0.f, tss = 0.f;
#pragma unroll
    for (int i = 0; i < 8; i++) { ts += red[i]; tss += red[8 + i]; }
    float mu   = ts * (1.0f / DM_);
    float var  = tss * (1.0f / DM_) - mu * mu;
    float rstd = rsqrtf(var + 1e-5f);
    float4 g  = ((const float4*)gamma)[tid];
    float4 bb = ((const float4*)beta)[tid];
    float4 o;
    o.x = tf32f((x.x - mu) * rstd * g.x + bb.x);
    o.y = tf32f((x.y - mu) * rstd * g.y + bb.y);
    o.z = tf32f((x.z - mu) * rstd * g.z + bb.z);
    o.w = tf32f((x.w - mu) * rstd * g.w + bb.w);
    ((float4*)(g_xln + (size_t)row * DM_))[tid] = o;
}

// ---------------- positional features phi[l, :], tf32 out --------------------
__global__ __launch_bounds__(256) void phi_kernel() {
    int l = blockIdx.x;
    float pos = (float)(L_ - 1 - l);
    for (int f = threadIdx.x; f < 512; f += blockDim.x) {
        float ex  = (float)(2 * f) / 1024.0f;
        float inv = powf(10000.0f, -ex);
        float a = pos * inv;
        float sn, cs;
        sincosf(a, &sn, &cs);
        g_phi[(size_t)l * DM_ + f]       = tf32f(sn);
        g_phi[(size_t)l * DM_ + 512 + f] = tf32f(cs);
    }
}

// ---------------- cp.async 4-stage tf32 GEMM: C = A @ B^T --------------------
// 128x128x32 CTA tile, 512 threads = 16 warps (4x4). Inputs pre-rounded tf32.
#define GST 36
#define STAGE_WORDS (128 * GST)
#define STAGES 4
#define GEMM_SMEM (STAGES * 2 * STAGE_WORDS * 4)   // 147456 B

__global__ __launch_bounds__(512, 1) void gemm_mma(const float* __restrict__ A,
                                                   const float* __restrict__ Bm,
                                                   float* __restrict__ C,
                                                   int M, int N, int K) {
    extern __shared__ uint32_t smem_u[];
    uint32_t* sA = smem_u;
    uint32_t* sB = smem_u + STAGES * STAGE_WORDS;
    uint32_t aAddr = smem_u32(sA);
    uint32_t bAddr = smem_u32(sB);

    int tid = threadIdx.x;
    int wid = tid >> 5, lane = tid & 31;
    int warp_m = wid >> 2, warp_n = wid & 3;
    int bm = blockIdx.y * 128, bn = blockIdx.x * 128;
    int lr  = tid >> 3;
    int lc4 = tid & 7;
    int qrow = lane >> 2, qcol = lane & 3;

    const float* Abase = A  + (size_t)(bm + lr) * K + lc4 * 4;
    const float* Bbase = Bm + (size_t)(bn + lr) * K + lc4 * 4;
    uint32_t dstOff = (lr * GST + lc4 * 4) * 4;

    float c[2][4][4];
#pragma unroll
    for (int mt = 0; mt < 2; mt++)
#pragma unroll
        for (int nt = 0; nt < 4; nt++)
#pragma unroll
            for (int e = 0; e < 4; e++) c[mt][nt][e] = 0.f;

    const int NC = K / 32;

    // prologue: issue stages 0..2
#pragma unroll
    for (int s = 0; s < STAGES - 1; s++) {
        uint32_t da = aAddr + s * (STAGE_WORDS * 4) + dstOff;
        uint32_t db = bAddr + s * (STAGE_WORDS * 4) + dstOff;
        cp16(da, Abase + s * 32);
        cp16(da + 64 * GST * 4, Abase + (size_t)64 * K + s * 32);
        cp16(db, Bbase + s * 32);
        cp16(db + 64 * GST * 4, Bbase + (size_t)64 * K + s * 32);
        cp_commit();
    }
    cp_wait2();
    __syncthreads();

    for (int kc = 0; kc < NC; kc++) {
        int st = kc & (STAGES - 1);
        const uint32_t* cA = sA + st * STAGE_WORDS;
        const uint32_t* cB = sB + st * STAGE_WORDS;
#pragma unroll
        for (int ks = 0; ks < 4; ks++) {
            int kk = ks * 8;
            uint32_t af[2][4], bf[4][2];
#pragma unroll
            for (int mt = 0; mt < 2; mt++) {
                int r = warp_m * 32 + mt * 16 + qrow;
                af[mt][0] = cA[r * GST + kk + qcol];
                af[mt][1] = cA[(r + 8) * GST + kk + qcol];
                af[mt][2] = cA[r * GST + kk + qcol + 4];
                af[mt][3] = cA[(r + 8) * GST + kk + qcol + 4];
            }
#pragma unroll
            for (int nt = 0; nt < 4; nt++) {
                int rn = warp_n * 32 + nt * 8 + qrow;
                bf[nt][0] = cB[rn * GST + kk + qcol];
                bf[nt][1] = cB[rn * GST + kk + qcol + 4];
            }
#pragma unroll
            for (int mt = 0; mt < 2; mt++)
#pragma unroll
                for (int nt = 0; nt < 4; nt++)
                    mma_tf32(c[mt][nt][0], c[mt][nt][1], c[mt][nt][2], c[mt][nt][3],
                             af[mt][0], af[mt][1], af[mt][2], af[mt][3],
                             bf[nt][0], bf[nt][1]);
        }
        // issue stage kc+3 into buffer (kc+3)%4 (computed 1 iter ago, all warps past sync)
        int kn = kc + STAGES - 1;
        if (kn < NC) {
            int sn = kn & (STAGES - 1);
            uint32_t da = aAddr + sn * (STAGE_WORDS * 4) + dstOff;
            uint32_t db = bAddr + sn * (STAGE_WORDS * 4) + dstOff;
            cp16(da, Abase + kn * 32);
            cp16(da + 64 * GST * 4, Abase + (size_t)64 * K + kn * 32);
            cp16(db, Bbase + kn * 32);
            cp16(db + 64 * GST * 4, Bbase + (size_t)64 * K + kn * 32);
        }
        cp_commit();          // always commit (possibly empty) to keep group math
        cp_wait2();           // stage kc+1 guaranteed complete
        __syncthreads();
    }

#pragma unroll
    for (int mt = 0; mt < 2; mt++) {
        int row = bm + warp_m * 32 + mt * 16 + qrow;
#pragma unroll
        for (int nt = 0; nt < 4; nt++) {
            int col = bn + warp_n * 32 + nt * 8 + 2 * qcol;
            *(float2*)(C + (size_t)row * N + col) = make_float2(c[mt][nt][0], c[mt][nt][1]);
            *(float2*)(C + (size_t)(row + 8) * N + col) = make_float2(c[mt][nt][2], c[mt][nt][3]);
        }
    }
}

// ---------------- mma-based fused relative flash attention -------------------
#define AW 68
#define AEW 132
#define ATT_SMEM ((7 * 64 * AW + 64 * AEW + 192) * 4)

__global__ __launch_bounds__(256) void attn_mma(const float* __restrict__ uvar,
                                                const float* __restrict__ vvar) {
    extern __shared__ float sm[];
    float* sQU = sm;
    float* sQV = sQU + 64 * AW;
    float* sK  = sQV + 64 * AW;
    float* sV  = sK  + 64 * AW;
    float* sR  = sV  + 64 * AW;
    float* sS  = sR  + 64 * AW;
    float* sP  = sS  + 64 * AW;
    float* sE  = sP  + 64 * AW;
    float* sm_m = sE + 64 * AEW;
    float* sm_l = sm_m + 64;
    float* sm_c = sm_l + 64;

    const uint32_t* uQU = (const uint32_t*)sQU;
    const uint32_t* uQV = (const uint32_t*)sQV;
    const uint32_t* uK  = (const uint32_t*)sK;
    const uint32_t* uV  = (const uint32_t*)sV;
    const uint32_t* uR  = (const uint32_t*)sR;
    const uint32_t* uP  = (const uint32_t*)sP;

    int i0 = blockIdx.x * 64;
    int b  = blockIdx.y >> 4;
    int h  = blockIdx.y & 15;
    int tid = threadIdx.x;
    int wid = tid >> 5, lane = tid & 31;
    int wm = wid >> 1, wn = wid & 1;
    int qrow = lane >> 2, qcol = lane & 3;

    for (int e = tid; e < 4096; e += 256) {
        int i = e >> 6, d = e & 63;
        float q = g_qkv[((size_t)(b * L_ + TAU_ + i0 + i)) * 3072 + h * 64 + d];
        sQU[i * AW + d] = tf32f(q + uvar[h * 64 + d]);
        sQV[i * AW + d] = tf32f(q + vvar[h * 64 + d]);
    }
    if (tid < 64) { sm_m[tid] = -INFINITY; sm_l[tid] = 0.f; }

    float o[4][4];
#pragma unroll
    for (int nt = 0; nt < 4; nt++)
#pragma unroll
        for (int e = 0; e < 4; e++) o[nt][e] = 0.f;

    int ntiles = (TAU_ + i0 + 63) / 64 + 1;
    int rnext = 448 - i0;

    for (int jt = 0; jt < ntiles; jt++) {
        int j0 = jt * 64;
        int rband = j0 + 448 - i0;
        __syncthreads();

        for (int e = tid; e < 4096; e += 256) {
            int j = e >> 6, d = e & 63;
            size_t base = ((size_t)(b * L_ + j0 + j)) * 3072 + h * 64 + d;
            sK[j * AW + d] = tf32f(g_qkv[base + 1024]);
            sV[d * AW + j] = tf32f(g_qkv[base + 2048]);
        }

        while (rnext < rband + 128) {
            for (int e = tid; e < 4096; e += 256) {
                int r = e >> 6, d = e & 63;
                int rr = rnext + r; rr = rr > (L_ - 1) ? (L_ - 1) : rr;
                sR[r * AW + d] = tf32f(g_R[(size_t)rr * DM_ + h * 64 + d]);
            }
            __syncthreads();
            int hf = (rnext >> 6) & 1;
            float ce[4][4];
#pragma unroll
            for (int nt = 0; nt < 4; nt++)
#pragma unroll
                for (int e = 0; e < 4; e++) ce[nt][e] = 0.f;
#pragma unroll
            for (int ks = 0; ks < 8; ks++) {
                int kk = ks * 8;
                int r = wm * 16 + qrow;
                uint32_t a0 = uQV[r * AW + kk + qcol];
                uint32_t a1 = uQV[(r + 8) * AW + kk + qcol];
                uint32_t a2 = uQV[r * AW + kk + qcol + 4];
                uint32_t a3 = uQV[(r + 8) * AW + kk + qcol + 4];
#pragma unroll
                for (int nt = 0; nt < 4; nt++) {
                    int rn = wn * 32 + nt * 8 + qrow;
                    uint32_t b0 = uR[rn * AW + kk + qcol];
                    uint32_t b1 = uR[rn * AW + kk + qcol + 4];
                    mma_tf32(ce[nt][0], ce[nt][1], ce[nt][2], ce[nt][3],
                             a0, a1, a2, a3, b0, b1);
                }
            }
            {
                int row = wm * 16 + qrow;
#pragma unroll
                for (int nt = 0; nt < 4; nt++) {
                    int col = hf * 64 + wn * 32 + nt * 8 + 2 * qcol;
                    sE[row * AEW + col]     = ce[nt][0];
                    sE[row * AEW + col + 1] = ce[nt][1];
                    sE[(row + 8) * AEW + col]     = ce[nt][2];
                    sE[(row + 8) * AEW + col + 1] = ce[nt][3];
                }
            }
            __syncthreads();
            rnext += 64;
        }

        {
            float cs[4][4];
#pragma unroll
            for (int nt = 0; nt < 4; nt++)
#pragma unroll
                for (int e = 0; e < 4; e++) cs[nt][e] = 0.f;
#pragma unroll
            for (int ks = 0; ks < 8; ks++) {
                int kk = ks * 8;
                int r = wm * 16 + qrow;
                uint32_t a0 = uQU[r * AW + kk + qcol];
                uint32_t a1 = uQU[(r + 8) * AW + kk + qcol];
                uint32_t a2 = uQU[r * AW + kk + qcol + 4];
                uint32_t a3 = uQU[(r + 8) * AW + kk + qcol + 4];
#pragma unroll
                for (int nt = 0; nt < 4; nt++) {
                    int rn = wn * 32 + nt * 8 + qrow;
                    uint32_t b0 = uK[rn * AW + kk + qcol];
                    uint32_t b1 = uK[rn * AW + kk + qcol + 4];
                    mma_tf32(cs[nt][0], cs[nt][1], cs[nt][2], cs[nt][3],
                             a0, a1, a2, a3, b0, b1);
                }
            }
            int row = wm * 16 + qrow;
#pragma unroll
            for (int nt = 0; nt < 4; nt++) {
                int col = wn * 32 + nt * 8 + 2 * qcol;
                sS[row * AW + col]     = cs[nt][0];
                sS[row * AW + col + 1] = cs[nt][1];
                sS[(row + 8) * AW + col]     = cs[nt][2];
                sS[(row + 8) * AW + col + 1] = cs[nt][3];
            }
        }
        __syncthreads();

        {
            int row = tid >> 2, cbase = (tid & 3) * 16;
            int gi = i0 + row;
            float oldm = sm_m[row];
            int sb = rband + 63 - row;
            float s16[16], mx = -INFINITY;
#pragma unroll
            for (int x = 0; x < 16; x++) {
                int jp = cbase + x;
                float s = (sS[row * AW + jp] + sE[row * AEW + ((sb + jp) & 127)]) * 0.125f;
                if (j0 + jp > TAU_ + gi) s = -1e30f;
                s16[x] = s;
                mx = fmaxf(mx, s);
            }
            mx = fmaxf(mx, __shfl_xor_sync(0xffffffffu, mx, 1));
            mx = fmaxf(mx, __shfl_xor_sync(0xffffffffu, mx, 2));
            float mnew = fmaxf(oldm, mx);
            float corr = __expf(oldm - mnew);
            float ps = 0.f;
#pragma unroll
            for (int x = 0; x < 16; x++) {
                float p = __expf(s16[x] - mnew);
                sP[row * AW + cbase + x] = tf32f(p);
                ps += p;
            }
            ps += __shfl_xor_sync(0xffffffffu, ps, 1);
            ps += __shfl_xor_sync(0xffffffffu, ps, 2);
            if ((tid & 3) == 0) {
                sm_m[row] = mnew;
                sm_l[row] = sm_l[row] * corr + ps;
                sm_c[row] = corr;
            }
        }
        __syncthreads();

        {
            float cr0 = sm_c[wm * 16 + qrow];
            float cr1 = sm_c[wm * 16 + qrow + 8];
#pragma unroll
            for (int nt = 0; nt < 4; nt++) {
                o[nt][0] *= cr0; o[nt][1] *= cr0;
                o[nt][2] *= cr1; o[nt][3] *= cr1;
            }
#pragma unroll
            for (int ks = 0; ks < 8; ks++) {
                int kk = ks * 8;
                int r = wm * 16 + qrow;
                uint32_t a0 = uP[r * AW + kk + qcol];
                uint32_t a1 = uP[(r + 8) * AW + kk + qcol];
                uint32_t a2 = uP[r * AW + kk + qcol + 4];
                uint32_t a3 = uP[(r + 8) * AW + kk + qcol + 4];
#pragma unroll
                for (int nt = 0; nt < 4; nt++) {
                    int rn = wn * 32 + nt * 8 + qrow;
                    uint32_t b0 = uV[rn * AW + kk + qcol];
                    uint32_t b1 = uV[rn * AW + kk + qcol + 4];
                    mma_tf32(o[nt][0], o[nt][1], o[nt][2], o[nt][3],
                             a0, a1, a2, a3, b0, b1);
                }
            }
        }
    }

    // write O (tf32-rounded: consumed by out-proj GEMM via cp.async)
    {
        int row = wm * 16 + qrow;
        float inv0 = 1.0f / sm_l[row];
        float inv1 = 1.0f / sm_l[row + 8];
#pragma unroll
        for (int nt = 0; nt < 4; nt++) {
            int col = h * 64 + wn * 32 + nt * 8 + 2 * qcol;
            *(float2*)(g_attn + ((size_t)(b * T_ + i0 + row)) * DM_ + col) =
                make_float2(tf32f(o[nt][0] * inv0), tf32f(o[nt][1] * inv0));
            *(float2*)(g_attn + ((size_t)(b * T_ + i0 + row + 8)) * DM_ + col) =
                make_float2(tf32f(o[nt][2] * inv1), tf32f(o[nt][3] * inv1));
        }
    }
}

// ---------------- host launcher ---------------------------------------------
extern "C" void kernel_launch(void* const* d_in, const int* in_sizes, int n_in,
                              void* d_out, int out_size) {
    const float* inputs = (const float*)d_in[0];
    const float* memory = (const float*)d_in[1];
    const float* w_qkv  = (const float*)d_in[2];
    const float* w_pos  = (const float*)d_in[3];
    const float* w_out  = (const float*)d_in[4];
    const float* uvar   = (const float*)d_in[5];
    const float* vvar   = (const float*)d_in[6];
    const float* gamma  = (const float*)d_in[7];
    const float* beta   = (const float*)d_in[8];
    float* out = (float*)d_out;

    float *xln, *qkv, *phi, *R, *attn, *wqkv, *wpos, *wout;
    cudaGetSymbolAddress((void**)&xln,  g_xln);
    cudaGetSymbolAddress((void**)&qkv,  g_qkv);
    cudaGetSymbolAddress((void**)&phi,  g_phi);
    cudaGetSymbolAddress((void**)&R,    g_R);
    cudaGetSymbolAddress((void**)&attn, g_attn);
    cudaGetSymbolAddress((void**)&wqkv, g_wqkv);
    cudaGetSymbolAddress((void**)&wpos, g_wpos);
    cudaGetSymbolAddress((void**)&wout, g_wout);

    cudaFuncSetAttribute(attn_mma,
                         cudaFuncAttributeMaxDynamicSharedMemorySize, ATT_SMEM);
    cudaFuncSetAttribute(gemm_mma,
                         cudaFuncAttributeMaxDynamicSharedMemorySize, GEMM_SMEM);

    // 0) round weights to tf32 (consumed raw via cp.async)
    round_tf32_kernel<<<(3 * DM_ * DM_ / 4 + 255) / 256, 256>>>(w_qkv, wqkv, 3 * DM_ * DM_ / 4);
    round_tf32_kernel<<<(DM_ * DM_ / 4 + 255) / 256, 256>>>(w_pos, wpos, DM_ * DM_ / 4);
    round_tf32_kernel<<<(DM_ * DM_ / 4 + 255) / 256, 256>>>(w_out, wout, DM_ * DM_ / 4);
    // 1) LayerNorm + concat (tf32 out)
    ln_kernel<<<B_ * L_, 256>>>(inputs, memory, gamma, beta);
    // 2) positional features (tf32 out)
    phi_kernel<<<L_, 256>>>();
    // 3) QKV = xln @ w_qkv^T   [4096 x 3072 x 1024]
    gemm_mma<<<dim3(3072 / 128, (B_ * L_) / 128), 512, GEMM_SMEM>>>(
        xln, wqkv, qkv, B_ * L_, 3 * DM_, DM_);
    // 4) R = phi @ w_pos^T     [1024 x 1024 x 1024]
    gemm_mma<<<dim3(DM_ / 128, L_ / 128), 512, GEMM_SMEM>>>(
        phi, wpos, R, L_, DM_, DM_);
    // 5) fused relative attention (tensor-core)
    attn_mma<<<dim3(T_ / 64, B_ * H_), 256, ATT_SMEM>>>(uvar, vvar);
    // 6) out = attn @ w_out^T  [2048 x 1024 x 1024]
    gemm_mma<<<dim3(DM_ / 128, (B_ * T_) / 128), 512, GEMM_SMEM>>>(
        attn, wout, out, B_ * T_, DM_, DM_);
}

// round 9
// speedup vs baseline: 3.1354x; 1.1151x over previous
#include <cuda_runtime.h>
#include <math.h>
#include <stdint.h>

#define B_ 4
#define T_ 512
#define TAU_ 512
#define L_ 1024
#define DM_ 1024
#define H_ 16
#define D_ 64

// ---------------- scratch (device globals; no allocations allowed) ----------
__device__ float g_xln[B_ * L_ * DM_];        // 16 MB  LN out (tf32-rounded)
__device__ float g_qkv[B_ * L_ * 3 * DM_];    // 48 MB  [B,L,3072]
__device__ float g_phi[L_ * DM_];             //  4 MB  (tf32-rounded)
__device__ float g_R[L_ * DM_];               //  4 MB  [L, H*D]
__device__ float g_attn[B_ * T_ * DM_];       //  8 MB  (tf32-rounded)
__device__ float g_wqkv[3 * DM_ * DM_];       // 12 MB  rounded weights
__device__ float g_wpos[DM_ * DM_];           //  4 MB
__device__ float g_wout[DM_ * DM_];           //  4 MB

__device__ __forceinline__ uint32_t tf32_rna(float f) {
    uint32_t r;
    asm("cvt.rna.tf32.f32 %0, %1;" : "=r"(r) : "f"(f));
    return r;
}
__device__ __forceinline__ float tf32f(float f) {
    return __uint_as_float(tf32_rna(f));
}
__device__ __forceinline__ uint32_t smem_u32(const void* p) {
    uint32_t a;
    asm("{ .reg .u64 t; cvta.to.shared.u64 t, %1; cvt.u32.u64 %0, t; }" : "=r"(a) : "l"(p));
    return a;
}
__device__ __forceinline__ void mma_tf32(float& c0, float& c1, float& c2, float& c3,
                                         uint32_t a0, uint32_t a1, uint32_t a2, uint32_t a3,
                                         uint32_t b0, uint32_t b1) {
    asm volatile(
        "mma.sync.aligned.m16n8k8.row.col.f32.tf32.tf32.f32 "
        "{%0,%1,%2,%3},{%4,%5,%6,%7},{%8,%9},{%0,%1,%2,%3};"
        : "+f"(c0), "+f"(c1), "+f"(c2), "+f"(c3)
        : "r"(a0), "r"(a1), "r"(a2), "r"(a3), "r"(b0), "r"(b1));
}
__device__ __forceinline__ void cp16(uint32_t dst, const void* src) {
    asm volatile("cp.async.cg.shared.global [%0], [%1], 16;" :: "r"(dst), "l"(src));
}
__device__ __forceinline__ void cp_commit() {
    asm volatile("cp.async.commit_group;" ::: "memory");
}
__device__ __forceinline__ void cp_wait2() {
    asm volatile("cp.async.wait_group 2;" ::: "memory");
}

// ---------------- round weights to tf32 --------------------------------------
__global__ __launch_bounds__(256) void round_tf32_kernel(const float* __restrict__ src,
                                                         float* __restrict__ dst, int n4) {
    int i = blockIdx.x * blockDim.x + threadIdx.x;
    if (i < n4) {
        float4 v = ((const float4*)src)[i];
        v.x = tf32f(v.x); v.y = tf32f(v.y); v.z = tf32f(v.z); v.w = tf32f(v.w);
        ((float4*)dst)[i] = v;
    }
}

// ---------------- LayerNorm over concat(memory, inputs), tf32 out ------------
__global__ __launch_bounds__(256) void ln_kernel(const float* __restrict__ inputs,
                          const float* __restrict__ memory,
                          const float* __restrict__ gamma,
                          const float* __restrict__ beta) {
    int row = blockIdx.x;
    int b = row >> 10, l = row & 1023;
    const float* src = (l < TAU_) ? memory + ((size_t)b * TAU_ + l) * DM_
                                  : inputs + ((size_t)b * T_ + (l - TAU_)) * DM_;
    int tid = threadIdx.x;
    float4 x = ((const float4*)src)[tid];
    float s  = x.x + x.y + x.z + x.w;
    float ss = x.x * x.x + x.y * x.y + x.z * x.z + x.w * x.w;
#pragma unroll
    for (int off = 16; off; off >>= 1) {
        s  += __shfl_xor_sync(0xffffffffu, s, off);
        ss += __shfl_xor_sync(0xffffffffu, ss, off);
    }
    __shared__ float red[16];
    int wid = tid >> 5, lane = tid & 31;
    if (lane == 0) { red[wid] = s; red[8 + wid] = ss; }
    __syncthreads();
    float ts = 0.f, tss = 0.f;
#pragma unroll
    for (int i = 0; i < 8; i++) { ts += red[i]; tss += red[8 + i]; }
    float mu   = ts * (1.0f / DM_);
    float var  = tss * (1.0f / DM_) - mu * mu;
    float rstd = rsqrtf(var + 1e-5f);
    float4 g  = ((const float4*)gamma)[tid];
    float4 bb = ((const float4*)beta)[tid];
    float4 o;
    o.x = tf32f((x.x - mu) * rstd * g.x + bb.x);
    o.y = tf32f((x.y - mu) * rstd * g.y + bb.y);
    o.z = tf32f((x.z - mu) * rstd * g.z + bb.z);
    o.w = tf32f((x.w - mu) * rstd * g.w + bb.w);
    ((float4*)(g_xln + (size_t)row * DM_))[tid] = o;
}

// ---------------- positional features phi[l, :], tf32 out --------------------
__global__ __launch_bounds__(256) void phi_kernel() {
    int l = blockIdx.x;
    float pos = (float)(L_ - 1 - l);
    for (int f = threadIdx.x; f < 512; f += blockDim.x) {
        float ex  = (float)(2 * f) / 1024.0f;
        float inv = powf(10000.0f, -ex);
        float a = pos * inv;
        float sn, cs;
        sincosf(a, &sn, &cs);
        g_phi[(size_t)l * DM_ + f]       = tf32f(sn);
        g_phi[(size_t)l * DM_ + 512 + f] = tf32f(cs);
    }
}

// ---------------- cp.async 4-stage tf32 GEMM: C = A @ B^T --------------------
#define GST 36
#define STAGE_WORDS (128 * GST)
#define STAGES 4
#define GEMM_SMEM (STAGES * 2 * STAGE_WORDS * 4)

__global__ __launch_bounds__(512, 1) void gemm_mma(const float* __restrict__ A,
                                                   const float* __restrict__ Bm,
                                                   float* __restrict__ C,
                                                   int M, int N, int K) {
    extern __shared__ uint32_t smem_u[];
    uint32_t* sA = smem_u;
    uint32_t* sB = smem_u + STAGES * STAGE_WORDS;
    uint32_t aAddr = smem_u32(sA);
    uint32_t bAddr = smem_u32(sB);

    int tid = threadIdx.x;
    int wid = tid >> 5, lane = tid & 31;
    int warp_m = wid >> 2, warp_n = wid & 3;
    int bm = blockIdx.y * 128, bn = blockIdx.x * 128;
    int lr  = tid >> 3;
    int lc4 = tid & 7;
    int qrow = lane >> 2, qcol = lane & 3;

    const float* Abase = A  + (size_t)(bm + lr) * K + lc4 * 4;
    const float* Bbase = Bm + (size_t)(bn + lr) * K + lc4 * 4;
    uint32_t dstOff = (lr * GST + lc4 * 4) * 4;

    float c[2][4][4];
#pragma unroll
    for (int mt = 0; mt < 2; mt++)
#pragma unroll
        for (int nt = 0; nt < 4; nt++)
#pragma unroll
            for (int e = 0; e < 4; e++) c[mt][nt][e] = 0.f;

    const int NC = K / 32;

#pragma unroll
    for (int s = 0; s < STAGES - 1; s++) {
        uint32_t da = aAddr + s * (STAGE_WORDS * 4) + dstOff;
        uint32_t db = bAddr + s * (STAGE_WORDS * 4) + dstOff;
        cp16(da, Abase + s * 32);
        cp16(da + 64 * GST * 4, Abase + (size_t)64 * K + s * 32);
        cp16(db, Bbase + s * 32);
        cp16(db + 64 * GST * 4, Bbase + (size_t)64 * K + s * 32);
        cp_commit();
    }
    cp_wait2();
    __syncthreads();

    for (int kc = 0; kc < NC; kc++) {
        int st = kc & (STAGES - 1);
        const uint32_t* cA = sA + st * STAGE_WORDS;
        const uint32_t* cB = sB + st * STAGE_WORDS;
#pragma unroll
        for (int ks = 0; ks < 4; ks++) {
            int kk = ks * 8;
            uint32_t af[2][4], bf[4][2];
#pragma unroll
            for (int mt = 0; mt < 2; mt++) {
                int r = warp_m * 32 + mt * 16 + qrow;
                af[mt][0] = cA[r * GST + kk + qcol];
                af[mt][1] = cA[(r + 8) * GST + kk + qcol];
                af[mt][2] = cA[r * GST + kk + qcol + 4];
                af[mt][3] = cA[(r + 8) * GST + kk + qcol + 4];
            }
#pragma unroll
            for (int nt = 0; nt < 4; nt++) {
                int rn = warp_n * 32 + nt * 8 + qrow;
                bf[nt][0] = cB[rn * GST + kk + qcol];
                bf[nt][1] = cB[rn * GST + kk + qcol + 4];
            }
#pragma unroll
            for (int mt = 0; mt < 2; mt++)
#pragma unroll
                for (int nt = 0; nt < 4; nt++)
                    mma_tf32(c[mt][nt][0], c[mt][nt][1], c[mt][nt][2], c[mt][nt][3],
                             af[mt][0], af[mt][1], af[mt][2], af[mt][3],
                             bf[nt][0], bf[nt][1]);
        }
        int kn = kc + STAGES - 1;
        if (kn < NC) {
            int sn = kn & (STAGES - 1);
            uint32_t da = aAddr + sn * (STAGE_WORDS * 4) + dstOff;
            uint32_t db = bAddr + sn * (STAGE_WORDS * 4) + dstOff;
            cp16(da, Abase + kn * 32);
            cp16(da + 64 * GST * 4, Abase + (size_t)64 * K + kn * 32);
            cp16(db, Bbase + kn * 32);
            cp16(db + 64 * GST * 4, Bbase + (size_t)64 * K + kn * 32);
        }
        cp_commit();
        cp_wait2();
        __syncthreads();
    }

#pragma unroll
    for (int mt = 0; mt < 2; mt++) {
        int row = bm + warp_m * 32 + mt * 16 + qrow;
#pragma unroll
        for (int nt = 0; nt < 4; nt++) {
            int col = bn + warp_n * 32 + nt * 8 + 2 * qcol;
            *(float2*)(C + (size_t)row * N + col) = make_float2(c[mt][nt][0], c[mt][nt][1]);
            *(float2*)(C + (size_t)(row + 8) * N + col) = make_float2(c[mt][nt][2], c[mt][nt][3]);
        }
    }
}

// ---------------- mma-based fused relative flash attention -------------------
// 104KB smem -> 2 CTAs/SM. One shared buffer cycles through R / K / V per tile;
// P overwrites S in place. V load hides behind the softmax phase.
#define AW 68
#define AEW 132
// floats: QU, QV, BUF, S  (4 * 64*AW) + E (64*AEW) + 192
#define ATT_SMEM ((4 * 64 * AW + 64 * AEW + 192) * 4)

__global__ __launch_bounds__(256, 2) void attn_mma(const float* __restrict__ uvar,
                                                   const float* __restrict__ vvar) {
    extern __shared__ float sm[];
    float* sQU = sm;                 // [64][AW] tf32 q+u
    float* sQV = sQU + 64 * AW;      // [64][AW] tf32 q+v
    float* sBf = sQV + 64 * AW;      // [64][AW] shared: R rows -> K tile -> V tile
    float* sS  = sBf + 64 * AW;      // [64][AW] scores, then probs in place
    float* sE  = sS  + 64 * AW;      // [64][AEW] E ring (128 cols)
    float* sm_m = sE + 64 * AEW;     // [64]
    float* sm_l = sm_m + 64;
    float* sm_c = sm_l + 64;

    const uint32_t* uQU = (const uint32_t*)sQU;
    const uint32_t* uQV = (const uint32_t*)sQV;
    const uint32_t* uBf = (const uint32_t*)sBf;
    const uint32_t* uS  = (const uint32_t*)sS;

    int i0 = blockIdx.x * 64;
    int b  = blockIdx.y >> 4;
    int h  = blockIdx.y & 15;
    int tid = threadIdx.x;
    int wid = tid >> 5, lane = tid & 31;
    int wm = wid >> 1, wn = wid & 1;
    int qrow = lane >> 2, qcol = lane & 3;

    // load q tiles, add u/v, convert tf32
    for (int e = tid; e < 4096; e += 256) {
        int i = e >> 6, d = e & 63;
        float q = g_qkv[((size_t)(b * L_ + TAU_ + i0 + i)) * 3072 + h * 64 + d];
        sQU[i * AW + d] = tf32f(q + uvar[h * 64 + d]);
        sQV[i * AW + d] = tf32f(q + vvar[h * 64 + d]);
    }
    if (tid < 64) { sm_m[tid] = -INFINITY; sm_l[tid] = 0.f; }

    float o[4][4];
#pragma unroll
    for (int nt = 0; nt < 4; nt++)
#pragma unroll
        for (int e = 0; e < 4; e++) o[nt][e] = 0.f;

    int ntiles = (TAU_ + i0 + 63) / 64 + 1;
    int rnext = 448 - i0;

    for (int jt = 0; jt < ntiles; jt++) {
        int j0 = jt * 64;
        int rband = j0 + 448 - i0;
        __syncthreads();                  // prev PV done with sBf(V) and sS(P)

        // ---- Phase A: R batches -> E ring halves ----
        while (rnext < rband + 128) {
            for (int e = tid; e < 4096; e += 256) {
                int r = e >> 6, d = e & 63;
                int rr = rnext + r; rr = rr > (L_ - 1) ? (L_ - 1) : rr;
                sBf[r * AW + d] = tf32f(g_R[(size_t)rr * DM_ + h * 64 + d]);
            }
            __syncthreads();
            int hf = (rnext >> 6) & 1;
            float ce[4][4];
#pragma unroll
            for (int nt = 0; nt < 4; nt++)
#pragma unroll
                for (int e = 0; e < 4; e++) ce[nt][e] = 0.f;
#pragma unroll
            for (int ks = 0; ks < 8; ks++) {
                int kk = ks * 8;
                int r = wm * 16 + qrow;
                uint32_t a0 = uQV[r * AW + kk + qcol];
                uint32_t a1 = uQV[(r + 8) * AW + kk + qcol];
                uint32_t a2 = uQV[r * AW + kk + qcol + 4];
                uint32_t a3 = uQV[(r + 8) * AW + kk + qcol + 4];
#pragma unroll
                for (int nt = 0; nt < 4; nt++) {
                    int rn = wn * 32 + nt * 8 + qrow;
                    uint32_t b0 = uBf[rn * AW + kk + qcol];
                    uint32_t b1 = uBf[rn * AW + kk + qcol + 4];
                    mma_tf32(ce[nt][0], ce[nt][1], ce[nt][2], ce[nt][3],
                             a0, a1, a2, a3, b0, b1);
                }
            }
            {
                int row = wm * 16 + qrow;
#pragma unroll
                for (int nt = 0; nt < 4; nt++) {
                    int col = hf * 64 + wn * 32 + nt * 8 + 2 * qcol;
                    sE[row * AEW + col]     = ce[nt][0];
                    sE[row * AEW + col + 1] = ce[nt][1];
                    sE[(row + 8) * AEW + col]     = ce[nt][2];
                    sE[(row + 8) * AEW + col + 1] = ce[nt][3];
                }
            }
            __syncthreads();              // E visible; sBf free
            rnext += 64;
        }

        // ---- Phase B: K tile -> S = QU @ K^T ----
        for (int e = tid; e < 4096; e += 256) {
            int j = e >> 6, d = e & 63;
            sBf[j * AW + d] = tf32f(g_qkv[((size_t)(b * L_ + j0 + j)) * 3072 + 1024 + h * 64 + d]);
        }
        __syncthreads();
        {
            float cs[4][4];
#pragma unroll
            for (int nt = 0; nt < 4; nt++)
#pragma unroll
                for (int e = 0; e < 4; e++) cs[nt][e] = 0.f;
#pragma unroll
            for (int ks = 0; ks < 8; ks++) {
                int kk = ks * 8;
                int r = wm * 16 + qrow;
                uint32_t a0 = uQU[r * AW + kk + qcol];
                uint32_t a1 = uQU[(r + 8) * AW + kk + qcol];
                uint32_t a2 = uQU[r * AW + kk + qcol + 4];
                uint32_t a3 = uQU[(r + 8) * AW + kk + qcol + 4];
#pragma unroll
                for (int nt = 0; nt < 4; nt++) {
                    int rn = wn * 32 + nt * 8 + qrow;
                    uint32_t b0 = uBf[rn * AW + kk + qcol];
                    uint32_t b1 = uBf[rn * AW + kk + qcol + 4];
                    mma_tf32(cs[nt][0], cs[nt][1], cs[nt][2], cs[nt][3],
                             a0, a1, a2, a3, b0, b1);
                }
            }
            int row = wm * 16 + qrow;
#pragma unroll
            for (int nt = 0; nt < 4; nt++) {
                int col = wn * 32 + nt * 8 + 2 * qcol;
                sS[row * AW + col]     = cs[nt][0];
                sS[row * AW + col + 1] = cs[nt][1];
                sS[(row + 8) * AW + col]     = cs[nt][2];
                sS[(row + 8) * AW + col + 1] = cs[nt][3];
            }
        }
        __syncthreads();                  // S ready; sBf(K) consumed

        // ---- Phase C: softmax (S -> P in place) + V load into sBf ----
        {
            int row = tid >> 2, cbase = (tid & 3) * 16;
            int gi = i0 + row;
            float oldm = sm_m[row];
            int sb = rband + 63 - row;
            float s16[16], mx = -INFINITY;
#pragma unroll
            for (int x = 0; x < 16; x++) {
                int jp = cbase + x;
                float s = (sS[row * AW + jp] + sE[row * AEW + ((sb + jp) & 127)]) * 0.125f;
                if (j0 + jp > TAU_ + gi) s = -1e30f;
                s16[x] = s;
                mx = fmaxf(mx, s);
            }
            mx = fmaxf(mx, __shfl_xor_sync(0xffffffffu, mx, 1));
            mx = fmaxf(mx, __shfl_xor_sync(0xffffffffu, mx, 2));
            float mnew = fmaxf(oldm, mx);
            float corr = __expf(oldm - mnew);
            float ps = 0.f;
#pragma unroll
            for (int x = 0; x < 16; x++) {
                float p = __expf(s16[x] - mnew);
                sS[row * AW + cbase + x] = tf32f(p);
                ps += p;
            }
            ps += __shfl_xor_sync(0xffffffffu, ps, 1);
            ps += __shfl_xor_sync(0xffffffffu, ps, 2);
            if ((tid & 3) == 0) {
                sm_m[row] = mnew;
                sm_l[row] = sm_l[row] * corr + ps;
                sm_c[row] = corr;
            }
        }
        // V tile (d-major) into sBf, overlapped with softmax above
        for (int e = tid; e < 4096; e += 256) {
            int j = e >> 6, d = e & 63;
            sBf[d * AW + j] = tf32f(g_qkv[((size_t)(b * L_ + j0 + j)) * 3072 + 2048 + h * 64 + d]);
        }
        __syncthreads();

        // ---- Phase D: O = O*corr + P @ V ----
        {
            float cr0 = sm_c[wm * 16 + qrow];
            float cr1 = sm_c[wm * 16 + qrow + 8];
#pragma unroll
            for (int nt = 0; nt < 4; nt++) {
                o[nt][0] *= cr0; o[nt][1] *= cr0;
                o[nt][2] *= cr1; o[nt][3] *= cr1;
            }
#pragma unroll
            for (int ks = 0; ks < 8; ks++) {
                int kk = ks * 8;
                int r = wm * 16 + qrow;
                uint32_t a0 = uS[r * AW + kk + qcol];
                uint32_t a1 = uS[(r + 8) * AW + kk + qcol];
                uint32_t a2 = uS[r * AW + kk + qcol + 4];
                uint32_t a3 = uS[(r + 8) * AW + kk + qcol + 4];
#pragma unroll
                for (int nt = 0; nt < 4; nt++) {
                    int rn = wn * 32 + nt * 8 + qrow;
                    uint32_t b0 = uBf[rn * AW + kk + qcol];
                    uint32_t b1 = uBf[rn * AW + kk + qcol + 4];
                    mma_tf32(o[nt][0], o[nt][1], o[nt][2], o[nt][3],
                             a0, a1, a2, a3, b0, b1);
                }
            }
        }
    }

    // write O (tf32-rounded: consumed by out-proj GEMM via cp.async)
    {
        int row = wm * 16 + qrow;
        float inv0 = 1.0f / sm_l[row];
        float inv1 = 1.0f / sm_l[row + 8];
#pragma unroll
        for (int nt = 0; nt < 4; nt++) {
            int col = h * 64 + wn * 32 + nt * 8 + 2 * qcol;
            *(float2*)(g_attn + ((size_t)(b * T_ + i0 + row)) * DM_ + col) =
                make_float2(tf32f(o[nt][0] * inv0), tf32f(o[nt][1] * inv0));
            *(float2*)(g_attn + ((size_t)(b * T_ + i0 + row + 8)) * DM_ + col) =
                make_float2(tf32f(o[nt][2] * inv1), tf32f(o[nt][3] * inv1));
        }
    }
}

// ---------------- host launcher ---------------------------------------------
extern "C" void kernel_launch(void* const* d_in, const int* in_sizes, int n_in,
                              void* d_out, int out_size) {
    const float* inputs = (const float*)d_in[0];
    const float* memory = (const float*)d_in[1];
    const float* w_qkv  = (const float*)d_in[2];
    const float* w_pos  = (const float*)d_in[3];
    const float* w_out  = (const float*)d_in[4];
    const float* uvar   = (const float*)d_in[5];
    const float* vvar   = (const float*)d_in[6];
    const float* gamma  = (const float*)d_in[7];
    const float* beta   = (const float*)d_in[8];
    float* out = (float*)d_out;

    float *xln, *qkv, *phi, *R, *attn, *wqkv, *wpos, *wout;
    cudaGetSymbolAddress((void**)&xln,  g_xln);
    cudaGetSymbolAddress((void**)&qkv,  g_qkv);
    cudaGetSymbolAddress((void**)&phi,  g_phi);
    cudaGetSymbolAddress((void**)&R,    g_R);
    cudaGetSymbolAddress((void**)&attn, g_attn);
    cudaGetSymbolAddress((void**)&wqkv, g_wqkv);
    cudaGetSymbolAddress((void**)&wpos, g_wpos);
    cudaGetSymbolAddress((void**)&wout, g_wout);

    cudaFuncSetAttribute(attn_mma,
                         cudaFuncAttributeMaxDynamicSharedMemorySize, ATT_SMEM);
    cudaFuncSetAttribute(gemm_mma,
                         cudaFuncAttributeMaxDynamicSharedMemorySize, GEMM_SMEM);

    // order chosen so harness ncu capture slot (#4) lands on the QKV GEMM
    // 1) LayerNorm + concat (tf32 out)
    ln_kernel<<<B_ * L_, 256>>>(inputs, memory, gamma, beta);
    // 2) positional features (tf32 out)
    phi_kernel<<<L_, 256>>>();
    // 3) round w_qkv
    round_tf32_kernel<<<(3 * DM_ * DM_ / 4 + 255) / 256, 256>>>(w_qkv, wqkv, 3 * DM_ * DM_ / 4);
    // 4) QKV = xln @ w_qkv^T   [4096 x 3072 x 1024]
    gemm_mma<<<dim3(3072 / 128, (B_ * L_) / 128), 512, GEMM_SMEM>>>(
        xln, wqkv, qkv, B_ * L_, 3 * DM_, DM_);
    // 5) round w_pos
    round_tf32_kernel<<<(DM_ * DM_ / 4 + 255) / 256, 256>>>(w_pos, wpos, DM_ * DM_ / 4);
    // 6) R = phi @ w_pos^T     [1024 x 1024 x 1024]
    gemm_mma<<<dim3(DM_ / 128, L_ / 128), 512, GEMM_SMEM>>>(
        phi, wpos, R, L_, DM_, DM_);
    // 7) fused relative attention (tensor-core)
    attn_mma<<<dim3(T_ / 64, B_ * H_), 256, ATT_SMEM>>>(uvar, vvar);
    // 8) round w_out
    round_tf32_kernel<<<(DM_ * DM_ / 4 + 255) / 256, 256>>>(w_out, wout, DM_ * DM_ / 4);
    // 9) out = attn @ w_out^T  [2048 x 1024 x 1024]
    gemm_mma<<<dim3(DM_ / 128, (B_ * T_) / 128), 512, GEMM_SMEM>>>(
        attn, wout, out, B_ * T_, DM_, DM_);
}

// round 10
// speedup vs baseline: 4.6673x; 1.4886x over previous
#include <cuda_runtime.h>
#include <cuda_fp16.h>
#include <math.h>
#include <stdint.h>

#define B_ 4
#define T_ 512
#define TAU_ 512
#define L_ 1024
#define DM_ 1024
#define H_ 16
#define D_ 64

// ---------------- scratch (device globals; no allocations allowed) ----------
__device__ __half g_xln[B_ * L_ * DM_];        //  8 MB  LN out (fp16)
__device__ __half g_qkv[B_ * L_ * 3 * DM_];    // 24 MB  [B,L,3072] fp16
__device__ __half g_phi[L_ * DM_];             //  2 MB
__device__ __half g_R[L_ * DM_];               //  2 MB
__device__ __half g_attn[B_ * T_ * DM_];       //  4 MB
__device__ __half g_wqkv[3 * DM_ * DM_];       //  6 MB  fp16 weights
__device__ __half g_wpos[DM_ * DM_];           //  2 MB
__device__ __half g_wout[DM_ * DM_];           //  2 MB

__device__ __forceinline__ uint32_t smem_u32(const void* p) {
    uint32_t a;
    asm("{ .reg .u64 t; cvta.to.shared.u64 t, %1; cvt.u32.u64 %0, t; }" : "=r"(a) : "l"(p));
    return a;
}
// fp16 mma, fp32 accum: m16n8k16
__device__ __forceinline__ void mma_f16(float& c0, float& c1, float& c2, float& c3,
                                        uint32_t a0, uint32_t a1, uint32_t a2, uint32_t a3,
                                        uint32_t b0, uint32_t b1) {
    asm volatile(
        "mma.sync.aligned.m16n8k16.row.col.f32.f16.f16.f32 "
        "{%0,%1,%2,%3},{%4,%5,%6,%7},{%8,%9},{%0,%1,%2,%3};"
        : "+f"(c0), "+f"(c1), "+f"(c2), "+f"(c3)
        : "r"(a0), "r"(a1), "r"(a2), "r"(a3), "r"(b0), "r"(b1));
}
__device__ __forceinline__ void cp16(uint32_t dst, const void* src) {
    asm volatile("cp.async.cg.shared.global [%0], [%1], 16;" :: "r"(dst), "l"(src));
}
__device__ __forceinline__ void cp_commit() {
    asm volatile("cp.async.commit_group;" ::: "memory");
}
__device__ __forceinline__ void cp_wait2() {
    asm volatile("cp.async.wait_group 2;" ::: "memory");
}

// ---------------- convert weights fp32 -> fp16 -------------------------------
__global__ __launch_bounds__(256) void round_h_kernel(const float* __restrict__ src,
                                                      __half* __restrict__ dst, int n4) {
    int i = blockIdx.x * blockDim.x + threadIdx.x;
    if (i < n4) {
        float4 v = ((const float4*)src)[i];
        ((__half2*)dst)[2 * i]     = __floats2half2_rn(v.x, v.y);
        ((__half2*)dst)[2 * i + 1] = __floats2half2_rn(v.z, v.w);
    }
}

// ---------------- LayerNorm over concat(memory, inputs), fp16 out ------------
__global__ __launch_bounds__(256) void ln_kernel(const float* __restrict__ inputs,
                          const float* __restrict__ memory,
                          const float* __restrict__ gamma,
                          const float* __restrict__ beta) {
    int row = blockIdx.x;
    int b = row >> 10, l = row & 1023;
    const float* src = (l < TAU_) ? memory + ((size_t)b * TAU_ + l) * DM_
                                  : inputs + ((size_t)b * T_ + (l - TAU_)) * DM_;
    int tid = threadIdx.x;
    float4 x = ((const float4*)src)[tid];
    float s  = x.x + x.y + x.z + x.w;
    float ss = x.x * x.x + x.y * x.y + x.z * x.z + x.w * x.w;
#pragma unroll
    for (int off = 16; off; off >>= 1) {
        s  += __shfl_xor_sync(0xffffffffu, s, off);
        ss += __shfl_xor_sync(0xffffffffu, ss, off);
    }
    __shared__ float red[16];
    int wid = tid >> 5, lane = tid & 31;
    if (lane == 0) { red[wid] = s; red[8 + wid] = ss; }
    __syncthreads();
    float ts = 0.f, tss = 0.f;
#pragma unroll
    for (int i = 0; i < 8; i++) { ts += red[i]; tss += red[8 + i]; }
    float mu   = ts * (1.0f / DM_);
    float var  = tss * (1.0f / DM_) - mu * mu;
    float rstd = rsqrtf(var + 1e-5f);
    float4 g  = ((const float4*)gamma)[tid];
    float4 bb = ((const float4*)beta)[tid];
    __half2* dst = (__half2*)(g_xln + (size_t)row * DM_);
    dst[2 * tid]     = __floats2half2_rn((x.x - mu) * rstd * g.x + bb.x,
                                         (x.y - mu) * rstd * g.y + bb.y);
    dst[2 * tid + 1] = __floats2half2_rn((x.z - mu) * rstd * g.z + bb.z,
                                         (x.w - mu) * rstd * g.w + bb.w);
}

// ---------------- positional features phi[l, :], fp16 out --------------------
__global__ __launch_bounds__(256) void phi_kernel() {
    int l = blockIdx.x;
    float pos = (float)(L_ - 1 - l);
    for (int f = threadIdx.x; f < 512; f += blockDim.x) {
        float ex  = (float)(2 * f) / 1024.0f;
        float inv = powf(10000.0f, -ex);
        float a = pos * inv;
        float sn, cs;
        sincosf(a, &sn, &cs);
        g_phi[(size_t)l * DM_ + f]       = __float2half_rn(sn);
        g_phi[(size_t)l * DM_ + 512 + f] = __float2half_rn(cs);
    }
}

// ---------------- cp.async 4-stage fp16 GEMM: C = A @ B^T --------------------
// 128x128x64 CTA K-chunk, 512 threads = 16 warps (4x4), warp tile 32x32.
// smem: per stage per matrix 128 rows x 36 words (64 fp16 data + pad).
#define GST 36
#define STAGE_WORDS (128 * GST)
#define STAGES 4
#define GEMM_SMEM (STAGES * 2 * STAGE_WORDS * 4)

template <bool HOUT>
__global__ __launch_bounds__(512, 1) void gemm_mma(const __half* __restrict__ A,
                                                   const __half* __restrict__ Bm,
                                                   void* __restrict__ Cv,
                                                   int M, int N, int K) {
    extern __shared__ uint32_t smem_u[];
    uint32_t* sA = smem_u;
    uint32_t* sB = smem_u + STAGES * STAGE_WORDS;
    uint32_t aAddr = smem_u32(sA);
    uint32_t bAddr = smem_u32(sB);

    int tid = threadIdx.x;
    int wid = tid >> 5, lane = tid & 31;
    int warp_m = wid >> 2, warp_n = wid & 3;
    int bm = blockIdx.y * 128, bn = blockIdx.x * 128;
    int lr  = tid >> 3;          // row 0..63 (+64 for second)
    int lc4 = tid & 7;           // 16B unit within 128B row
    int qrow = lane >> 2, qcol = lane & 3;

    const __half* Abase = A  + (size_t)(bm + lr) * K + lc4 * 8;
    const __half* Bbase = Bm + (size_t)(bn + lr) * K + lc4 * 8;
    uint32_t dstOff = (lr * GST + lc4 * 4) * 4;

    float c[2][4][4];
#pragma unroll
    for (int mt = 0; mt < 2; mt++)
#pragma unroll
        for (int nt = 0; nt < 4; nt++)
#pragma unroll
            for (int e = 0; e < 4; e++) c[mt][nt][e] = 0.f;

    const int NC = K / 64;

#pragma unroll
    for (int s = 0; s < STAGES - 1; s++) {
        uint32_t da = aAddr + s * (STAGE_WORDS * 4) + dstOff;
        uint32_t db = bAddr + s * (STAGE_WORDS * 4) + dstOff;
        cp16(da, Abase + s * 64);
        cp16(da + 64 * GST * 4, Abase + (size_t)64 * K + s * 64);
        cp16(db, Bbase + s * 64);
        cp16(db + 64 * GST * 4, Bbase + (size_t)64 * K + s * 64);
        cp_commit();
    }
    cp_wait2();
    __syncthreads();

    for (int kc = 0; kc < NC; kc++) {
        int st = kc & (STAGES - 1);
        const uint32_t* cA = sA + st * STAGE_WORDS;
        const uint32_t* cB = sB + st * STAGE_WORDS;
#pragma unroll
        for (int ks = 0; ks < 4; ks++) {        // k16 per step
            int kk = ks * 8;
            uint32_t af[2][4], bf[4][2];
#pragma unroll
            for (int mt = 0; mt < 2; mt++) {
                int r = warp_m * 32 + mt * 16 + qrow;
                af[mt][0] = cA[r * GST + kk + qcol];
                af[mt][1] = cA[(r + 8) * GST + kk + qcol];
                af[mt][2] = cA[r * GST + kk + qcol + 4];
                af[mt][3] = cA[(r + 8) * GST + kk + qcol + 4];
            }
#pragma unroll
            for (int nt = 0; nt < 4; nt++) {
                int rn = warp_n * 32 + nt * 8 + qrow;
                bf[nt][0] = cB[rn * GST + kk + qcol];
                bf[nt][1] = cB[rn * GST + kk + qcol + 4];
            }
#pragma unroll
            for (int mt = 0; mt < 2; mt++)
#pragma unroll
                for (int nt = 0; nt < 4; nt++)
                    mma_f16(c[mt][nt][0], c[mt][nt][1], c[mt][nt][2], c[mt][nt][3],
                            af[mt][0], af[mt][1], af[mt][2], af[mt][3],
                            bf[nt][0], bf[nt][1]);
        }
        int kn = kc + STAGES - 1;
        if (kn < NC) {
            int sn = kn & (STAGES - 1);
            uint32_t da = aAddr + sn * (STAGE_WORDS * 4) + dstOff;
            uint32_t db = bAddr + sn * (STAGE_WORDS * 4) + dstOff;
            cp16(da, Abase + kn * 64);
            cp16(da + 64 * GST * 4, Abase + (size_t)64 * K + kn * 64);
            cp16(db, Bbase + kn * 64);
            cp16(db + 64 * GST * 4, Bbase + (size_t)64 * K + kn * 64);
        }
        cp_commit();
        cp_wait2();
        __syncthreads();
    }

#pragma unroll
    for (int mt = 0; mt < 2; mt++) {
        int row = bm + warp_m * 32 + mt * 16 + qrow;
#pragma unroll
        for (int nt = 0; nt < 4; nt++) {
            int col = bn + warp_n * 32 + nt * 8 + 2 * qcol;
            if (HOUT) {
                __half* Ch = (__half*)Cv;
                *(__half2*)(Ch + (size_t)row * N + col) =
                    __floats2half2_rn(c[mt][nt][0], c[mt][nt][1]);
                *(__half2*)(Ch + (size_t)(row + 8) * N + col) =
                    __floats2half2_rn(c[mt][nt][2], c[mt][nt][3]);
            } else {
                float* Cf = (float*)Cv;
                *(float2*)(Cf + (size_t)row * N + col) = make_float2(c[mt][nt][0], c[mt][nt][1]);
                *(float2*)(Cf + (size_t)(row + 8) * N + col) = make_float2(c[mt][nt][2], c[mt][nt][3]);
            }
        }
    }
}

// ---------------- fp16 mma fused relative flash attention --------------------
// 87KB smem -> 2 CTAs/SM. Shared buffer cycles R -> K -> V per tile.
// Scores/E/softmax stay fp32; tile operands + P are fp16.
#define AWW 36      // word stride of fp16 tiles (64 halves + pad)
#define AWH 72      // half stride
#define ASW 68      // fp32 score row stride
#define AEW 132     // fp32 E ring stride
// bytes: 3 fp16 tiles (QU,QV,BUF) + P + S + E + 3*64 floats
#define ATT_SMEM ((4 * 64 * AWW + 64 * ASW + 64 * AEW + 192) * 4)

__global__ __launch_bounds__(256, 2) void attn_mma(const float* __restrict__ uvar,
                                                   const float* __restrict__ vvar) {
    extern __shared__ float sm[];
    __half* hQU = (__half*)sm;                         // [64][AWH]
    __half* hQV = hQU + 64 * AWH;                      // [64][AWH]
    __half* hBf = hQV + 64 * AWH;                      // [64][AWH] R->K->V
    __half* hP  = hBf + 64 * AWH;                      // [64][AWH] probs
    float* sS   = (float*)(hP + 64 * AWH);             // [64][ASW] scores
    float* sE   = sS + 64 * ASW;                       // [64][AEW] E ring
    float* sm_m = sE + 64 * AEW;
    float* sm_l = sm_m + 64;
    float* sm_c = sm_l + 64;

    const uint32_t* uQU = (const uint32_t*)hQU;
    const uint32_t* uQV = (const uint32_t*)hQV;
    const uint32_t* uBf = (const uint32_t*)hBf;
    const uint32_t* uP  = (const uint32_t*)hP;

    int i0 = blockIdx.x * 64;
    int b  = blockIdx.y >> 4;
    int h  = blockIdx.y & 15;
    int tid = threadIdx.x;
    int wid = tid >> 5, lane = tid & 31;
    int wm = wid >> 1, wn = wid & 1;
    int qrow = lane >> 2, qcol = lane & 3;

    // load q tiles, add u/v (fp32), store fp16
    for (int e = tid; e < 4096; e += 256) {
        int i = e >> 6, d = e & 63;
        float q = __half2float(g_qkv[((size_t)(b * L_ + TAU_ + i0 + i)) * 3072 + h * 64 + d]);
        hQU[i * AWH + d] = __float2half_rn(q + uvar[h * 64 + d]);
        hQV[i * AWH + d] = __float2half_rn(q + vvar[h * 64 + d]);
    }
    if (tid < 64) { sm_m[tid] = -INFINITY; sm_l[tid] = 0.f; }

    float o[4][4];
#pragma unroll
    for (int nt = 0; nt < 4; nt++)
#pragma unroll
        for (int e = 0; e < 4; e++) o[nt][e] = 0.f;

    int ntiles = (TAU_ + i0 + 63) / 64 + 1;
    int rnext = 448 - i0;

    for (int jt = 0; jt < ntiles; jt++) {
        int j0 = jt * 64;
        int rband = j0 + 448 - i0;
        __syncthreads();                  // prev PV done with hBf(V), hP

        // ---- Phase A: R batches -> E ring halves ----
        while (rnext < rband + 128) {
            for (int e = tid; e < 4096; e += 256) {
                int r = e >> 6, d = e & 63;
                int rr = rnext + r; rr = rr > (L_ - 1) ? (L_ - 1) : rr;
                hBf[r * AWH + d] = g_R[(size_t)rr * DM_ + h * 64 + d];
            }
            __syncthreads();
            int hf = (rnext >> 6) & 1;
            float ce[4][4];
#pragma unroll
            for (int nt = 0; nt < 4; nt++)
#pragma unroll
                for (int e = 0; e < 4; e++) ce[nt][e] = 0.f;
#pragma unroll
            for (int ks = 0; ks < 4; ks++) {
                int kk = ks * 8;
                int r = wm * 16 + qrow;
                uint32_t a0 = uQV[r * AWW + kk + qcol];
                uint32_t a1 = uQV[(r + 8) * AWW + kk + qcol];
                uint32_t a2 = uQV[r * AWW + kk + qcol + 4];
                uint32_t a3 = uQV[(r + 8) * AWW + kk + qcol + 4];
#pragma unroll
                for (int nt = 0; nt < 4; nt++) {
                    int rn = wn * 32 + nt * 8 + qrow;
                    uint32_t b0 = uBf[rn * AWW + kk + qcol];
                    uint32_t b1 = uBf[rn * AWW + kk + qcol + 4];
                    mma_f16(ce[nt][0], ce[nt][1], ce[nt][2], ce[nt][3],
                            a0, a1, a2, a3, b0, b1);
                }
            }
            {
                int row = wm * 16 + qrow;
#pragma unroll
                for (int nt = 0; nt < 4; nt++) {
                    int col = hf * 64 + wn * 32 + nt * 8 + 2 * qcol;
                    sE[row * AEW + col]     = ce[nt][0];
                    sE[row * AEW + col + 1] = ce[nt][1];
                    sE[(row + 8) * AEW + col]     = ce[nt][2];
                    sE[(row + 8) * AEW + col + 1] = ce[nt][3];
                }
            }
            __syncthreads();
            rnext += 64;
        }

        // ---- Phase B: K tile -> S = QU @ K^T ----
        for (int e = tid; e < 4096; e += 256) {
            int j = e >> 6, d = e & 63;
            hBf[j * AWH + d] = g_qkv[((size_t)(b * L_ + j0 + j)) * 3072 + 1024 + h * 64 + d];
        }
        __syncthreads();
        {
            float cs[4][4];
#pragma unroll
            for (int nt = 0; nt < 4; nt++)
#pragma unroll
                for (int e = 0; e < 4; e++) cs[nt][e] = 0.f;
#pragma unroll
            for (int ks = 0; ks < 4; ks++) {
                int kk = ks * 8;
                int r = wm * 16 + qrow;
                uint32_t a0 = uQU[r * AWW + kk + qcol];
                uint32_t a1 = uQU[(r + 8) * AWW + kk + qcol];
                uint32_t a2 = uQU[r * AWW + kk + qcol + 4];
                uint32_t a3 = uQU[(r + 8) * AWW + kk + qcol + 4];
#pragma unroll
                for (int nt = 0; nt < 4; nt++) {
                    int rn = wn * 32 + nt * 8 + qrow;
                    uint32_t b0 = uBf[rn * AWW + kk + qcol];
                    uint32_t b1 = uBf[rn * AWW + kk + qcol + 4];
                    mma_f16(cs[nt][0], cs[nt][1], cs[nt][2], cs[nt][3],
                            a0, a1, a2, a3, b0, b1);
                }
            }
            int row = wm * 16 + qrow;
#pragma unroll
            for (int nt = 0; nt < 4; nt++) {
                int col = wn * 32 + nt * 8 + 2 * qcol;
                sS[row * ASW + col]     = cs[nt][0];
                sS[row * ASW + col + 1] = cs[nt][1];
                sS[(row + 8) * ASW + col]     = cs[nt][2];
                sS[(row + 8) * ASW + col + 1] = cs[nt][3];
            }
        }
        __syncthreads();                  // S ready; hBf(K) consumed

        // ---- Phase C: softmax (S -> hP) + V load into hBf ----
        {
            int row = tid >> 2, cbase = (tid & 3) * 16;
            int gi = i0 + row;
            float oldm = sm_m[row];
            int sb = rband + 63 - row;
            float s16[16], mx = -INFINITY;
#pragma unroll
            for (int x = 0; x < 16; x++) {
                int jp = cbase + x;
                float s = (sS[row * ASW + jp] + sE[row * AEW + ((sb + jp) & 127)]) * 0.125f;
                if (j0 + jp > TAU_ + gi) s = -1e30f;
                s16[x] = s;
                mx = fmaxf(mx, s);
            }
            mx = fmaxf(mx, __shfl_xor_sync(0xffffffffu, mx, 1));
            mx = fmaxf(mx, __shfl_xor_sync(0xffffffffu, mx, 2));
            float mnew = fmaxf(oldm, mx);
            float corr = __expf(oldm - mnew);
            float ps = 0.f;
#pragma unroll
            for (int x = 0; x < 16; x += 2) {
                float p0 = __expf(s16[x] - mnew);
                float p1 = __expf(s16[x + 1] - mnew);
                *(__half2*)(hP + row * AWH + cbase + x) = __floats2half2_rn(p0, p1);
                ps += p0 + p1;
            }
            ps += __shfl_xor_sync(0xffffffffu, ps, 1);
            ps += __shfl_xor_sync(0xffffffffu, ps, 2);
            if ((tid & 3) == 0) {
                sm_m[row] = mnew;
                sm_l[row] = sm_l[row] * corr + ps;
                sm_c[row] = corr;
            }
        }
        // V tile (d-major) into hBf, overlapped with softmax above
        for (int e = tid; e < 4096; e += 256) {
            int j = e >> 6, d = e & 63;
            hBf[d * AWH + j] = g_qkv[((size_t)(b * L_ + j0 + j)) * 3072 + 2048 + h * 64 + d];
        }
        __syncthreads();

        // ---- Phase D: O = O*corr + P @ V ----
        {
            float cr0 = sm_c[wm * 16 + qrow];
            float cr1 = sm_c[wm * 16 + qrow + 8];
#pragma unroll
            for (int nt = 0; nt < 4; nt++) {
                o[nt][0] *= cr0; o[nt][1] *= cr0;
                o[nt][2] *= cr1; o[nt][3] *= cr1;
            }
#pragma unroll
            for (int ks = 0; ks < 4; ks++) {
                int kk = ks * 8;
                int r = wm * 16 + qrow;
                uint32_t a0 = uP[r * AWW + kk + qcol];
                uint32_t a1 = uP[(r + 8) * AWW + kk + qcol];
                uint32_t a2 = uP[r * AWW + kk + qcol + 4];
                uint32_t a3 = uP[(r + 8) * AWW + kk + qcol + 4];
#pragma unroll
                for (int nt = 0; nt < 4; nt++) {
                    int rn = wn * 32 + nt * 8 + qrow;
                    uint32_t b0 = uBf[rn * AWW + kk + qcol];
                    uint32_t b1 = uBf[rn * AWW + kk + qcol + 4];
                    mma_f16(o[nt][0], o[nt][1], o[nt][2], o[nt][3],
                            a0, a1, a2, a3, b0, b1);
                }
            }
        }
    }

    // write O fp16 (consumed by out-proj GEMM)
    {
        int row = wm * 16 + qrow;
        float inv0 = 1.0f / sm_l[row];
        float inv1 = 1.0f / sm_l[row + 8];
#pragma unroll
        for (int nt = 0; nt < 4; nt++) {
            int col = h * 64 + wn * 32 + nt * 8 + 2 * qcol;
            *(__half2*)(g_attn + ((size_t)(b * T_ + i0 + row)) * DM_ + col) =
                __floats2half2_rn(o[nt][0] * inv0, o[nt][1] * inv0);
            *(__half2*)(g_attn + ((size_t)(b * T_ + i0 + row + 8)) * DM_ + col) =
                __floats2half2_rn(o[nt][2] * inv1, o[nt][3] * inv1);
        }
    }
}

// ---------------- host launcher ---------------------------------------------
extern "C" void kernel_launch(void* const* d_in, const int* in_sizes, int n_in,
                              void* d_out, int out_size) {
    const float* inputs = (const float*)d_in[0];
    const float* memory = (const float*)d_in[1];
    const float* w_qkv  = (const float*)d_in[2];
    const float* w_pos  = (const float*)d_in[3];
    const float* w_out  = (const float*)d_in[4];
    const float* uvar   = (const float*)d_in[5];
    const float* vvar   = (const float*)d_in[6];
    const float* gamma  = (const float*)d_in[7];
    const float* beta   = (const float*)d_in[8];
    float* out = (float*)d_out;

    __half *xln, *qkv, *phi, *R, *attn, *wqkv, *wpos, *wout;
    cudaGetSymbolAddress((void**)&xln,  g_xln);
    cudaGetSymbolAddress((void**)&qkv,  g_qkv);
    cudaGetSymbolAddress((void**)&phi,  g_phi);
    cudaGetSymbolAddress((void**)&R,    g_R);
    cudaGetSymbolAddress((void**)&attn, g_attn);
    cudaGetSymbolAddress((void**)&wqkv, g_wqkv);
    cudaGetSymbolAddress((void**)&wpos, g_wpos);
    cudaGetSymbolAddress((void**)&wout, g_wout);

    cudaFuncSetAttribute(attn_mma,
                         cudaFuncAttributeMaxDynamicSharedMemorySize, ATT_SMEM);
    cudaFuncSetAttribute(gemm_mma<true>,
                         cudaFuncAttributeMaxDynamicSharedMemorySize, GEMM_SMEM);
    cudaFuncSetAttribute(gemm_mma<false>,
                         cudaFuncAttributeMaxDynamicSharedMemorySize, GEMM_SMEM);

    // order keeps ncu capture slot (#4) on the QKV GEMM
    // 1) LayerNorm + concat (fp16 out)
    ln_kernel<<<B_ * L_, 256>>>(inputs, memory, gamma, beta);
    // 2) positional features (fp16 out)
    phi_kernel<<<L_, 256>>>();
    // 3) w_qkv -> fp16
    round_h_kernel<<<(3 * DM_ * DM_ / 4 + 255) / 256, 256>>>(w_qkv, wqkv, 3 * DM_ * DM_ / 4);
    // 4) QKV = xln @ w_qkv^T   [4096 x 3072 x 1024]
    gemm_mma<true><<<dim3(3072 / 128, (B_ * L_) / 128), 512, GEMM_SMEM>>>(
        xln, wqkv, qkv, B_ * L_, 3 * DM_, DM_);
    // 5) w_pos -> fp16
    round_h_kernel<<<(DM_ * DM_ / 4 + 255) / 256, 256>>>(w_pos, wpos, DM_ * DM_ / 4);
    // 6) R = phi @ w_pos^T     [1024 x 1024 x 1024]
    gemm_mma<true><<<dim3(DM_ / 128, L_ / 128), 512, GEMM_SMEM>>>(
        phi, wpos, R, L_, DM_, DM_);
    // 7) fused relative attention (fp16 tensor-core)
    attn_mma<<<dim3(T_ / 64, B_ * H_), 256, ATT_SMEM>>>(uvar, vvar);
    // 8) w_out -> fp16
    round_h_kernel<<<(DM_ * DM_ / 4 + 255) / 256, 256>>>(w_out, wout, DM_ * DM_ / 4);
    // 9) out = attn @ w_out^T  [2048 x 1024 x 1024]  (fp32 out)
    gemm_mma<false><<<dim3(DM_ / 128, (B_ * T_) / 128), 512, GEMM_SMEM>>>(
        attn, wout, out, B_ * T_, DM_, DM_);
}

// round 11
// speedup vs baseline: 6.2933x; 1.3484x over previous
#include <cuda_runtime.h>
#include <cuda_fp16.h>
#include <math.h>
#include <stdint.h>

#define B_ 4
#define T_ 512
#define TAU_ 512
#define L_ 1024
#define DM_ 1024
#define H_ 16
#define D_ 64

// ---------------- scratch (device globals; no allocations allowed) ----------
__device__ __half g_xln[B_ * L_ * DM_];        //  8 MB  LN out (fp16)
__device__ __half g_qkv[B_ * L_ * 3 * DM_];    // 24 MB  [B,L,3072] fp16
__device__ __half g_phi[L_ * DM_];             //  2 MB
__device__ __half g_R[L_ * DM_];               //  2 MB
__device__ __half g_attn[B_ * T_ * DM_];       //  4 MB
__device__ __half g_wqkv[3 * DM_ * DM_];       //  6 MB  fp16 weights
__device__ __half g_wpos[DM_ * DM_];           //  2 MB
__device__ __half g_wout[DM_ * DM_];           //  2 MB

__device__ __forceinline__ uint32_t smem_u32(const void* p) {
    uint32_t a;
    asm("{ .reg .u64 t; cvta.to.shared.u64 t, %1; cvt.u32.u64 %0, t; }" : "=r"(a) : "l"(p));
    return a;
}
// fp16 mma, fp32 accum: m16n8k16
__device__ __forceinline__ void mma_f16(float& c0, float& c1, float& c2, float& c3,
                                        uint32_t a0, uint32_t a1, uint32_t a2, uint32_t a3,
                                        uint32_t b0, uint32_t b1) {
    asm volatile(
        "mma.sync.aligned.m16n8k16.row.col.f32.f16.f16.f32 "
        "{%0,%1,%2,%3},{%4,%5,%6,%7},{%8,%9},{%0,%1,%2,%3};"
        : "+f"(c0), "+f"(c1), "+f"(c2), "+f"(c3)
        : "r"(a0), "r"(a1), "r"(a2), "r"(a3), "r"(b0), "r"(b1));
}
__device__ __forceinline__ void cp16(uint32_t dst, const void* src) {
    asm volatile("cp.async.cg.shared.global [%0], [%1], 16;" :: "r"(dst), "l"(src));
}
__device__ __forceinline__ void cp_commit() {
    asm volatile("cp.async.commit_group;" ::: "memory");
}
__device__ __forceinline__ void cp_wait1() {
    asm volatile("cp.async.wait_group 1;" ::: "memory");
}

// ---------------- convert weights fp32 -> fp16 -------------------------------
__global__ __launch_bounds__(256) void round_h_kernel(const float* __restrict__ src,
                                                      __half* __restrict__ dst, int n4) {
    int i = blockIdx.x * blockDim.x + threadIdx.x;
    if (i < n4) {
        float4 v = ((const float4*)src)[i];
        ((__half2*)dst)[2 * i]     = __floats2half2_rn(v.x, v.y);
        ((__half2*)dst)[2 * i + 1] = __floats2half2_rn(v.z, v.w);
    }
}

// ---------------- LayerNorm over concat(memory, inputs), fp16 out ------------
__global__ __launch_bounds__(256) void ln_kernel(const float* __restrict__ inputs,
                          const float* __restrict__ memory,
                          const float* __restrict__ gamma,
                          const float* __restrict__ beta) {
    int row = blockIdx.x;
    int b = row >> 10, l = row & 1023;
    const float* src = (l < TAU_) ? memory + ((size_t)b * TAU_ + l) * DM_
                                  : inputs + ((size_t)b * T_ + (l - TAU_)) * DM_;
    int tid = threadIdx.x;
    float4 x = ((const float4*)src)[tid];
    float s  = x.x + x.y + x.z + x.w;
    float ss = x.x * x.x + x.y * x.y + x.z * x.z + x.w * x.w;
#pragma unroll
    for (int off = 16; off; off >>= 1) {
        s  += __shfl_xor_sync(0xffffffffu, s, off);
        ss += __shfl_xor_sync(0xffffffffu, ss, off);
    }
    __shared__ float red[16];
    int wid = tid >> 5, lane = tid & 31;
    if (lane == 0) { red[wid] = s; red[8 + wid] = ss; }
    __syncthreads();
    float ts = 0.f, tss = 0.f;
#pragma unroll
    for (int i = 0; i < 8; i++) { ts += red[i]; tss += red[8 + i]; }
    float mu   = ts * (1.0f / DM_);
    float var  = tss * (1.0f / DM_) - mu * mu;
    float rstd = rsqrtf(var + 1e-5f);
    float4 g  = ((const float4*)gamma)[tid];
    float4 bb = ((const float4*)beta)[tid];
    __half2* dst = (__half2*)(g_xln + (size_t)row * DM_);
    dst[2 * tid]     = __floats2half2_rn((x.x - mu) * rstd * g.x + bb.x,
                                         (x.y - mu) * rstd * g.y + bb.y);
    dst[2 * tid + 1] = __floats2half2_rn((x.z - mu) * rstd * g.z + bb.z,
                                         (x.w - mu) * rstd * g.w + bb.w);
}

// ---------------- positional features phi[l, :], fp16 out --------------------
__global__ __launch_bounds__(256) void phi_kernel() {
    int l = blockIdx.x;
    float pos = (float)(L_ - 1 - l);
    for (int f = threadIdx.x; f < 512; f += blockDim.x) {
        float ex  = (float)(2 * f) / 1024.0f;
        float inv = powf(10000.0f, -ex);
        float a = pos * inv;
        float sn, cs;
        sincosf(a, &sn, &cs);
        g_phi[(size_t)l * DM_ + f]       = __float2half_rn(sn);
        g_phi[(size_t)l * DM_ + 512 + f] = __float2half_rn(cs);
    }
}

// ---------------- cp.async 3-stage fp16 GEMM: C = A @ B^T --------------------
// 128x128x64 CTA K-chunk, 128 threads = 4 warps (2x2), warp tile 64x64.
// Halves LDS traffic vs 32x32 warp tiles (each A/B slice read by 2 warps not 4).
#define GST 36
#define STAGE_WORDS (128 * GST)
#define STAGE_BYTES (STAGE_WORDS * 4)
#define STAGES 3
#define GEMM_SMEM (STAGES * 2 * STAGE_WORDS * 4)   // 110592 B -> 2 CTAs/SM

#define GEMM_ISSUE(kcc, st) do {                                            \
    const __half* Ag = A  + (size_t)bm * K + (kcc) * 64;                    \
    const __half* Bg = Bm + (size_t)bn * K + (kcc) * 64;                    \
    uint32_t baseA = aAddr + (st) * STAGE_BYTES;                            \
    uint32_t baseB = bAddr + (st) * STAGE_BYTES;                            \
    _Pragma("unroll")                                                       \
    for (int p = 0; p < 8; p++) {                                           \
        int sgm = tid + 128 * p;                                            \
        int row = sgm >> 3, cs = sgm & 7;                                   \
        uint32_t off = (uint32_t)(row * GST + cs * 4) * 4;                  \
        cp16(baseA + off, Ag + (size_t)row * K + cs * 8);                   \
        cp16(baseB + off, Bg + (size_t)row * K + cs * 8);                   \
    }                                                                       \
} while (0)

template <bool HOUT>
__global__ __launch_bounds__(128, 2) void gemm_mma(const __half* __restrict__ A,
                                                   const __half* __restrict__ Bm,
                                                   void* __restrict__ Cv,
                                                   int M, int N, int K) {
    extern __shared__ uint32_t smem_u[];
    uint32_t* sA = smem_u;
    uint32_t* sB = smem_u + STAGES * STAGE_WORDS;
    uint32_t aAddr = smem_u32(sA);
    uint32_t bAddr = smem_u32(sB);

    int tid = threadIdx.x;
    int wid = tid >> 5, lane = tid & 31;
    int warp_m = wid >> 1, warp_n = wid & 1;
    int bm = blockIdx.y * 128, bn = blockIdx.x * 128;
    int qrow = lane >> 2, qcol = lane & 3;

    float c[4][8][4];
#pragma unroll
    for (int mt = 0; mt < 4; mt++)
#pragma unroll
        for (int nt = 0; nt < 8; nt++)
#pragma unroll
            for (int e = 0; e < 4; e++) c[mt][nt][e] = 0.f;

    const int NC = K / 64;

    // prologue: stages 0,1
    GEMM_ISSUE(0, 0); cp_commit();
    GEMM_ISSUE(1, 1); cp_commit();

    int st = 0;
    for (int kc = 0; kc < NC; kc++) {
        cp_wait1();                  // stage kc complete
        __syncthreads();
        const uint32_t* cA = sA + st * STAGE_WORDS;
        const uint32_t* cB = sB + st * STAGE_WORDS;
#pragma unroll
        for (int ks = 0; ks < 4; ks++) {
            int kk = ks * 8;
            uint32_t af[4][4];
#pragma unroll
            for (int mt = 0; mt < 4; mt++) {
                int r = warp_m * 64 + mt * 16 + qrow;
                af[mt][0] = cA[r * GST + kk + qcol];
                af[mt][1] = cA[(r + 8) * GST + kk + qcol];
                af[mt][2] = cA[r * GST + kk + qcol + 4];
                af[mt][3] = cA[(r + 8) * GST + kk + qcol + 4];
            }
#pragma unroll
            for (int nt = 0; nt < 8; nt++) {
                int rn = warp_n * 64 + nt * 8 + qrow;
                uint32_t b0 = cB[rn * GST + kk + qcol];
                uint32_t b1 = cB[rn * GST + kk + qcol + 4];
#pragma unroll
                for (int mt = 0; mt < 4; mt++)
                    mma_f16(c[mt][nt][0], c[mt][nt][1], c[mt][nt][2], c[mt][nt][3],
                            af[mt][0], af[mt][1], af[mt][2], af[mt][3], b0, b1);
            }
        }
        int kn = kc + 2;
        if (kn < NC) {
            int sn = st + 2; if (sn >= STAGES) sn -= STAGES;
            GEMM_ISSUE(kn, sn);
        }
        cp_commit();
        __syncthreads();             // all warps done with stage st before reuse
        if (++st == STAGES) st = 0;
    }

#pragma unroll
    for (int mt = 0; mt < 4; mt++) {
        int row = bm + warp_m * 64 + mt * 16 + qrow;
#pragma unroll
        for (int nt = 0; nt < 8; nt++) {
            int col = bn + warp_n * 64 + nt * 8 + 2 * qcol;
            if (HOUT) {
                __half* Ch = (__half*)Cv;
                *(__half2*)(Ch + (size_t)row * N + col) =
                    __floats2half2_rn(c[mt][nt][0], c[mt][nt][1]);
                *(__half2*)(Ch + (size_t)(row + 8) * N + col) =
                    __floats2half2_rn(c[mt][nt][2], c[mt][nt][3]);
            } else {
                float* Cf = (float*)Cv;
                *(float2*)(Cf + (size_t)row * N + col) = make_float2(c[mt][nt][0], c[mt][nt][1]);
                *(float2*)(Cf + (size_t)(row + 8) * N + col) = make_float2(c[mt][nt][2], c[mt][nt][3]);
            }
        }
    }
}

// ---------------- fp16 mma fused relative flash attention --------------------
// 87KB smem -> 2 CTAs/SM. Shared buffer cycles R -> K -> V per tile.
// All tile loads vectorized 16B; V transpose uses sub-word-merged STS.U16.
#define AWW 36      // word stride of fp16 tiles (64 halves + pad)
#define AWH 72      // half stride (144 B, 16B-aligned)
#define ASW 68      // fp32 score row stride
#define AEW 132     // fp32 E ring stride
#define ATT_SMEM ((4 * 64 * AWW + 64 * ASW + 64 * AEW + 192) * 4)

__global__ __launch_bounds__(256, 2) void attn_mma(const float* __restrict__ uvar,
                                                   const float* __restrict__ vvar) {
    extern __shared__ float sm[];
    __half* hQU = (__half*)sm;                         // [64][AWH]
    __half* hQV = hQU + 64 * AWH;                      // [64][AWH]
    __half* hBf = hQV + 64 * AWH;                      // [64][AWH] R->K->V
    __half* hP  = hBf + 64 * AWH;                      // [64][AWH] probs
    float* sS   = (float*)(hP + 64 * AWH);             // [64][ASW] scores
    float* sE   = sS + 64 * ASW;                       // [64][AEW] E ring
    float* sm_m = sE + 64 * AEW;
    float* sm_l = sm_m + 64;
    float* sm_c = sm_l + 64;

    const uint32_t* uQU = (const uint32_t*)hQU;
    const uint32_t* uQV = (const uint32_t*)hQV;
    const uint32_t* uBf = (const uint32_t*)hBf;
    const uint32_t* uP  = (const uint32_t*)hP;

    int i0 = blockIdx.x * 64;
    int b  = blockIdx.y >> 4;
    int h  = blockIdx.y & 15;
    int tid = threadIdx.x;
    int wid = tid >> 5, lane = tid & 31;
    int wm = wid >> 1, wn = wid & 1;
    int qrow = lane >> 2, qcol = lane & 3;

    // load q tiles (16B vectorized), add u/v in fp32, store fp16
#pragma unroll
    for (int p = 0; p < 2; p++) {
        int s = tid + 256 * p;            // 0..511
        int i = s >> 3, seg = s & 7;
        uint4 q4 = *(const uint4*)(g_qkv + ((size_t)(b * L_ + TAU_ + i0 + i)) * 3072 + h * 64 + seg * 8);
        const __half* qh = (const __half*)&q4;
        const float* up = uvar + h * 64 + seg * 8;
        const float* vp = vvar + h * 64 + seg * 8;
        __half2 ou[4], ov[4];
#pragma unroll
        for (int k = 0; k < 4; k++) {
            float q0 = __half2float(qh[2 * k]), q1 = __half2float(qh[2 * k + 1]);
            ou[k] = __floats2half2_rn(q0 + up[2 * k], q1 + up[2 * k + 1]);
            ov[k] = __floats2half2_rn(q0 + vp[2 * k], q1 + vp[2 * k + 1]);
        }
        *(uint4*)(hQU + i * AWH + seg * 8) = *(uint4*)ou;
        *(uint4*)(hQV + i * AWH + seg * 8) = *(uint4*)ov;
    }
    if (tid < 64) { sm_m[tid] = -INFINITY; sm_l[tid] = 0.f; }

    float o[4][4];
#pragma unroll
    for (int nt = 0; nt < 4; nt++)
#pragma unroll
        for (int e = 0; e < 4; e++) o[nt][e] = 0.f;

    int ntiles = (TAU_ + i0 + 63) / 64 + 1;
    int rnext = 448 - i0;

    for (int jt = 0; jt < ntiles; jt++) {
        int j0 = jt * 64;
        int rband = j0 + 448 - i0;
        __syncthreads();                  // prev PV done with hBf(V), hP

        // ---- Phase A: R batches -> E ring halves ----
        while (rnext < rband + 128) {
#pragma unroll
            for (int p = 0; p < 2; p++) {
                int s = tid + 256 * p;
                int r = s >> 3, seg = s & 7;
                int rr = rnext + r; rr = rr > (L_ - 1) ? (L_ - 1) : rr;
                *(uint4*)(hBf + r * AWH + seg * 8) =
                    *(const uint4*)(g_R + (size_t)rr * DM_ + h * 64 + seg * 8);
            }
            __syncthreads();
            int hf = (rnext >> 6) & 1;
            float ce[4][4];
#pragma unroll
            for (int nt = 0; nt < 4; nt++)
#pragma unroll
                for (int e = 0; e < 4; e++) ce[nt][e] = 0.f;
#pragma unroll
            for (int ks = 0; ks < 4; ks++) {
                int kk = ks * 8;
                int r = wm * 16 + qrow;
                uint32_t a0 = uQV[r * AWW + kk + qcol];
                uint32_t a1 = uQV[(r + 8) * AWW + kk + qcol];
                uint32_t a2 = uQV[r * AWW + kk + qcol + 4];
                uint32_t a3 = uQV[(r + 8) * AWW + kk + qcol + 4];
#pragma unroll
                for (int nt = 0; nt < 4; nt++) {
                    int rn = wn * 32 + nt * 8 + qrow;
                    uint32_t b0 = uBf[rn * AWW + kk + qcol];
                    uint32_t b1 = uBf[rn * AWW + kk + qcol + 4];
                    mma_f16(ce[nt][0], ce[nt][1], ce[nt][2], ce[nt][3],
                            a0, a1, a2, a3, b0, b1);
                }
            }
            {
                int row = wm * 16 + qrow;
#pragma unroll
                for (int nt = 0; nt < 4; nt++) {
                    int col = hf * 64 + wn * 32 + nt * 8 + 2 * qcol;
                    sE[row * AEW + col]     = ce[nt][0];
                    sE[row * AEW + col + 1] = ce[nt][1];
                    sE[(row + 8) * AEW + col]     = ce[nt][2];
                    sE[(row + 8) * AEW + col + 1] = ce[nt][3];
                }
            }
            __syncthreads();
            rnext += 64;
        }

        // ---- Phase B: K tile (16B copies) -> S = QU @ K^T ----
#pragma unroll
        for (int p = 0; p < 2; p++) {
            int s = tid + 256 * p;
            int j = s >> 3, seg = s & 7;
            *(uint4*)(hBf + j * AWH + seg * 8) =
                *(const uint4*)(g_qkv + ((size_t)(b * L_ + j0 + j)) * 3072 + 1024 + h * 64 + seg * 8);
        }
        __syncthreads();
        {
            float cs[4][4];
#pragma unroll
            for (int nt = 0; nt < 4; nt++)
#pragma unroll
                for (int e = 0; e < 4; e++) cs[nt][e] = 0.f;
#pragma unroll
            for (int ks = 0; ks < 4; ks++) {
                int kk = ks * 8;
                int r = wm * 16 + qrow;
                uint32_t a0 = uQU[r * AWW + kk + qcol];
                uint32_t a1 = uQU[(r + 8) * AWW + kk + qcol];
                uint32_t a2 = uQU[r * AWW + kk + qcol + 4];
                uint32_t a3 = uQU[(r + 8) * AWW + kk + qcol + 4];
#pragma unroll
                for (int nt = 0; nt < 4; nt++) {
                    int rn = wn * 32 + nt * 8 + qrow;
                    uint32_t b0 = uBf[rn * AWW + kk + qcol];
                    uint32_t b1 = uBf[rn * AWW + kk + qcol + 4];
                    mma_f16(cs[nt][0], cs[nt][1], cs[nt][2], cs[nt][3],
                            a0, a1, a2, a3, b0, b1);
                }
            }
            int row = wm * 16 + qrow;
#pragma unroll
            for (int nt = 0; nt < 4; nt++) {
                int col = wn * 32 + nt * 8 + 2 * qcol;
                sS[row * ASW + col]     = cs[nt][0];
                sS[row * ASW + col + 1] = cs[nt][1];
                sS[(row + 8) * ASW + col]     = cs[nt][2];
                sS[(row + 8) * ASW + col + 1] = cs[nt][3];
            }
        }
        __syncthreads();                  // S ready; hBf(K) consumed

        // ---- Phase C: softmax (S -> hP) + V load into hBf ----
        {
            int row = tid >> 2, cbase = (tid & 3) * 16;
            int gi = i0 + row;
            float oldm = sm_m[row];
            int sb = rband + 63 - row;
            float s16[16], mx = -INFINITY;
#pragma unroll
            for (int x = 0; x < 16; x++) {
                int jp = cbase + x;
                float s = (sS[row * ASW + jp] + sE[row * AEW + ((sb + jp) & 127)]) * 0.125f;
                if (j0 + jp > TAU_ + gi) s = -1e30f;
                s16[x] = s;
                mx = fmaxf(mx, s);
            }
            mx = fmaxf(mx, __shfl_xor_sync(0xffffffffu, mx, 1));
            mx = fmaxf(mx, __shfl_xor_sync(0xffffffffu, mx, 2));
            float mnew = fmaxf(oldm, mx);
            float corr = __expf(oldm - mnew);
            float ps = 0.f;
#pragma unroll
            for (int x = 0; x < 16; x += 2) {
                float p0 = __expf(s16[x] - mnew);
                float p1 = __expf(s16[x + 1] - mnew);
                *(__half2*)(hP + row * AWH + cbase + x) = __floats2half2_rn(p0, p1);
                ps += p0 + p1;
            }
            ps += __shfl_xor_sync(0xffffffffu, ps, 1);
            ps += __shfl_xor_sync(0xffffffffu, ps, 2);
            if ((tid & 3) == 0) {
                sm_m[row] = mnew;
                sm_l[row] = sm_l[row] * corr + ps;
                sm_c[row] = corr;
            }
        }
        // V tile (transpose to d-major): vectorized LDG, half-merged STS
#pragma unroll
        for (int p = 0; p < 2; p++) {
            int s = tid + 256 * p;
            int j = s & 63, dg = s >> 6;   // consecutive lanes -> consecutive j
            uint4 v4 = *(const uint4*)(g_qkv + ((size_t)(b * L_ + j0 + j)) * 3072 + 2048 + h * 64 + dg * 8);
            const __half* vh = (const __half*)&v4;
#pragma unroll
            for (int k = 0; k < 8; k++)
                hBf[(dg * 8 + k) * AWH + j] = vh[k];
        }
        __syncthreads();

        // ---- Phase D: O = O*corr + P @ V ----
        {
            float cr0 = sm_c[wm * 16 + qrow];
            float cr1 = sm_c[wm * 16 + qrow + 8];
#pragma unroll
            for (int nt = 0; nt < 4; nt++) {
                o[nt][0] *= cr0; o[nt][1] *= cr0;
                o[nt][2] *= cr1; o[nt][3] *= cr1;
            }
#pragma unroll
            for (int ks = 0; ks < 4; ks++) {
                int kk = ks * 8;
                int r = wm * 16 + qrow;
                uint32_t a0 = uP[r * AWW + kk + qcol];
                uint32_t a1 = uP[(r + 8) * AWW + kk + qcol];
                uint32_t a2 = uP[r * AWW + kk + qcol + 4];
                uint32_t a3 = uP[(r + 8) * AWW + kk + qcol + 4];
#pragma unroll
                for (int nt = 0; nt < 4; nt++) {
                    int rn = wn * 32 + nt * 8 + qrow;
                    uint32_t b0 = uBf[rn * AWW + kk + qcol];
                    uint32_t b1 = uBf[rn * AWW + kk + qcol + 4];
                    mma_f16(o[nt][0], o[nt][1], o[nt][2], o[nt][3],
                            a0, a1, a2, a3, b0, b1);
                }
            }
        }
    }

    // write O fp16 (consumed by out-proj GEMM)
    {
        int row = wm * 16 + qrow;
        float inv0 = 1.0f / sm_l[row];
        float inv1 = 1.0f / sm_l[row + 8];
#pragma unroll
        for (int nt = 0; nt < 4; nt++) {
            int col = h * 64 + wn * 32 + nt * 8 + 2 * qcol;
            *(__half2*)(g_attn + ((size_t)(b * T_ + i0 + row)) * DM_ + col) =
                __floats2half2_rn(o[nt][0] * inv0, o[nt][1] * inv0);
            *(__half2*)(g_attn + ((size_t)(b * T_ + i0 + row + 8)) * DM_ + col) =
                __floats2half2_rn(o[nt][2] * inv1, o[nt][3] * inv1);
        }
    }
}

// ---------------- host launcher ---------------------------------------------
extern "C" void kernel_launch(void* const* d_in, const int* in_sizes, int n_in,
                              void* d_out, int out_size) {
    const float* inputs = (const float*)d_in[0];
    const float* memory = (const float*)d_in[1];
    const float* w_qkv  = (const float*)d_in[2];
    const float* w_pos  = (const float*)d_in[3];
    const float* w_out  = (const float*)d_in[4];
    const float* uvar   = (const float*)d_in[5];
    const float* vvar   = (const float*)d_in[6];
    const float* gamma  = (const float*)d_in[7];
    const float* beta   = (const float*)d_in[8];
    float* out = (float*)d_out;

    __half *xln, *qkv, *phi, *R, *attn, *wqkv, *wpos, *wout;
    cudaGetSymbolAddress((void**)&xln,  g_xln);
    cudaGetSymbolAddress((void**)&qkv,  g_qkv);
    cudaGetSymbolAddress((void**)&phi,  g_phi);
    cudaGetSymbolAddress((void**)&R,    g_R);
    cudaGetSymbolAddress((void**)&attn, g_attn);
    cudaGetSymbolAddress((void**)&wqkv, g_wqkv);
    cudaGetSymbolAddress((void**)&wpos, g_wpos);
    cudaGetSymbolAddress((void**)&wout, g_wout);

    cudaFuncSetAttribute(attn_mma,
                         cudaFuncAttributeMaxDynamicSharedMemorySize, ATT_SMEM);
    cudaFuncSetAttribute(gemm_mma<true>,
                         cudaFuncAttributeMaxDynamicSharedMemorySize, GEMM_SMEM);
    cudaFuncSetAttribute(gemm_mma<false>,
                         cudaFuncAttributeMaxDynamicSharedMemorySize, GEMM_SMEM);

    // order keeps ncu capture slot (#4) on the QKV GEMM
    // 1) LayerNorm + concat (fp16 out)
    ln_kernel<<<B_ * L_, 256>>>(inputs, memory, gamma, beta);
    // 2) positional features (fp16 out)
    phi_kernel<<<L_, 256>>>();
    // 3) w_qkv -> fp16
    round_h_kernel<<<(3 * DM_ * DM_ / 4 + 255) / 256, 256>>>(w_qkv, wqkv, 3 * DM_ * DM_ / 4);
    // 4) QKV = xln @ w_qkv^T   [4096 x 3072 x 1024]
    gemm_mma<true><<<dim3(3072 / 128, (B_ * L_) / 128), 128, GEMM_SMEM>>>(
        xln, wqkv, qkv, B_ * L_, 3 * DM_, DM_);
    // 5) w_pos -> fp16
    round_h_kernel<<<(DM_ * DM_ / 4 + 255) / 256, 256>>>(w_pos, wpos, DM_ * DM_ / 4);
    // 6) R = phi @ w_pos^T     [1024 x 1024 x 1024]
    gemm_mma<true><<<dim3(DM_ / 128, L_ / 128), 128, GEMM_SMEM>>>(
        phi, wpos, R, L_, DM_, DM_);
    // 7) fused relative attention (fp16 tensor-core)
    attn_mma<<<dim3(T_ / 64, B_ * H_), 256, ATT_SMEM>>>(uvar, vvar);
    // 8) w_out -> fp16
    round_h_kernel<<<(DM_ * DM_ / 4 + 255) / 256, 256>>>(w_out, wout, DM_ * DM_ / 4);
    // 9) out = attn @ w_out^T  [2048 x 1024 x 1024]  (fp32 out)
    gemm_mma<false><<<dim3(DM_ / 128, (B_ * T_) / 128), 128, GEMM_SMEM>>>(
        attn, wout, out, B_ * T_, DM_, DM_);
}